// round 13
// baseline (speedup 1.0000x reference)
#include <cuda_runtime.h>
#include <math.h>

#define NLAYER 8
#define HH 4
#define DD 64
#define QKD 64
#define VDIM 128
#define TT 17
#define FFND 12

typedef unsigned long long u64;

// ---------------- f32x2 helpers ----------------
__device__ __forceinline__ u64 pk2(float a, float b) {
  u64 r;
  asm("mov.b64 %0, {%1,%2};" : "=l"(r) : "f"(a), "f"(b));
  return r;
}
__device__ __forceinline__ void up2(u64 v, float& a, float& b) {
  asm("mov.b64 {%0,%1}, %2;" : "=f"(a), "=f"(b) : "l"(v));
}
__device__ __forceinline__ void fma2(u64& d_, u64 a, u64 b) {
  asm("fma.rn.f32x2 %0, %1, %2, %0;" : "+l"(d_) : "l"(a), "l"(b));
}
__device__ __forceinline__ void ld128(const float* p, u64& a, u64& b) {
  float4 v = *reinterpret_cast<const float4*>(p);
  a = pk2(v.x, v.y);
  b = pk2(v.z, v.w);
}
__device__ __forceinline__ u64 ld64(const float* p) {
  return *reinterpret_cast<const u64*>(p);
}
__device__ __forceinline__ void st64(float* p, u64 v) {
  *reinterpret_cast<u64*>(p) = v;
}

// ---------------- precomputed tables ----------------
__device__ float g_sin[TT][16];
__device__ float g_cos[TT][16];
__device__ float g_dmask[HH][TT][20];  // padded rows (16B-aligned)

__global__ void init_tables_kernel() {
  if (threadIdx.x != 0 || blockIdx.x != 0) return;
  double angle[16];
  for (int u = 0; u < 8; ++u) {
    double a = pow(10000.0, -(double)u / 7.0);
    angle[2 * u] = a;
    angle[2 * u + 1] = a;
  }
  for (int t = 0; t < TT; ++t)
    for (int d2 = 0; d2 < 16; ++d2) {
      g_sin[t][d2] = (float)sin((double)t * angle[d2]);
      g_cos[t][d2] = (float)cos((double)t * angle[d2]);
    }
  double l0 = log(1.0 / 32.0), l1 = log(1.0 / 512.0);
  for (int h = 0; h < HH; ++h) {
    double gamma = 1.0 - exp(l0 + (double)h * (l1 - l0) / 3.0);
    for (int n = 0; n < TT; ++n) {
      double vals[TT];
      double rs = 0.0;
      for (int m = 0; m < TT; ++m) {
        double v_ = 0.0;
        if (n >= m) v_ = pow(gamma, (double)(n - m));
        vals[m] = v_;
        rs += v_;
      }
      double inv = 1.0 / sqrt(rs);
      for (int m = 0; m < TT; ++m) g_dmask[h][n][m] = (float)(vals[m] * inv);
      for (int m = TT; m < 20; ++m) g_dmask[h][n][m] = 0.f;
    }
  }
}

// ---------------- shared memory (vector bases 16B-aligned) ----------------
struct Smem {
  float h[TT][68];       // residual [t][ch]
  float xlT[DD][20];     // LN out [ch][t], t=17 pad 0
  float qT[DD][20];      // post-rotary q [ch][t]
  float kT[DD][20];      // post-rotary scaled k [ch][t]
  float sT[HH][TT][20];  // scores [h][m][n], n=17 col zeroed
  float f[TT][FFND];
  float sin_[TT][16], cos_[TT][16];
  float mu[TT], rs[TT];
  float z[16];
};
union SmemU {
  Smem a;
  float img[3 * 32 * 32];
};

// warp-parallel LN stats: warp w covers tokens 4w..4w+3 (+ token 16 on warp 0)
__device__ __forceinline__ void ln_stats(Smem& S, int d) {
  int wrp = d >> 5, lane = d & 31;
  int cnt = (wrp == 0) ? 5 : 4;
  for (int i = 0; i < cnt; ++i) {
    int t = (i == 4) ? 16 : (wrp * 4 + i);
    float a, b;
    up2(ld64(&S.h[t][2 * lane]), a, b);
    float s1 = a + b, s2 = a * a + b * b;
#pragma unroll
    for (int off = 16; off; off >>= 1) {
      s1 += __shfl_xor_sync(0xffffffffu, s1, off);
      s2 += __shfl_xor_sync(0xffffffffu, s2, off);
    }
    if (lane == 0) {
      float mu = s1 * (1.f / DD);
      S.mu[t] = mu;
      S.rs[t] = rsqrtf(s2 * (1.f / DD) - mu * mu + 1e-5f);
    }
  }
}

__global__ __launch_bounds__(128, 5) void vit_kernel(
    const float* __restrict__ x, const float* __restrict__ patch_w,
    const float* __restrict__ patch_b, const float* __restrict__ cls,
    const float* __restrict__ pos, const float* __restrict__ Wq,
    const float* __restrict__ Wk, const float* __restrict__ Wv,
    const float* __restrict__ Wg, const float* __restrict__ Wo,
    const float* __restrict__ ln1_s, const float* __restrict__ ln1_b,
    const float* __restrict__ w1, const float* __restrict__ b1,
    const float* __restrict__ w2, const float* __restrict__ b2,
    const float* __restrict__ ln2_s, const float* __restrict__ ln2_b,
    const float* __restrict__ lnf_s, const float* __restrict__ lnf_b,
    const float* __restrict__ neck_w, const float* __restrict__ neck_b,
    const float* __restrict__ head_w, const float* __restrict__ head_b,
    float* __restrict__ out) {
  extern __shared__ char smem_raw[];
  SmemU& U = *reinterpret_cast<SmemU*>(smem_raw);
  Smem& S = U.a;

  const int b = blockIdx.x;
  const int d = threadIdx.x;  // 0..127
  const int half = d >> 6;
  const int ch = d & 63;
  const int lane = d & 31;

  const float* xb = x + (size_t)b * 3072;
  for (int i = d; i < 3072; i += 128) U.img[i] = xb[i];
  __syncthreads();

  // ---------------- patch embedding ----------------
  float tokcol[8];
  const int pt0 = half ? 9 : 1;
  for (int i = 0; i < 8; ++i) {
    int t = pt0 + i;
    int p = t - 1, pr = p >> 2, pc = p & 3;
    float acc = patch_b[ch] + pos[t * DD + ch];
    u64 accp = 0;
    for (int c = 0; c < 3; ++c) {
#pragma unroll
      for (int i2 = 0; i2 < 8; ++i2) {
        const float* row = &U.img[c * 1024 + (pr * 8 + i2) * 32 + pc * 8];
        const float* wrow = &patch_w[(c * 64 + i2 * 8) * DD + ch];
        u64 r0, r1, r2, r3;
        ld128(row, r0, r1);
        ld128(row + 4, r2, r3);
        fma2(accp, r0, pk2(wrow[0], wrow[DD]));
        fma2(accp, r1, pk2(wrow[2 * DD], wrow[3 * DD]));
        fma2(accp, r2, pk2(wrow[4 * DD], wrow[5 * DD]));
        fma2(accp, r3, pk2(wrow[6 * DD], wrow[7 * DD]));
      }
    }
    float pa, pb;
    up2(accp, pa, pb);
    tokcol[i] = acc + pa + pb;
  }
  __syncthreads();  // img reads complete
#pragma unroll
  for (int i = 0; i < 8; ++i) S.h[pt0 + i][ch] = tokcol[i];
  if (half == 0) S.h[0][ch] = cls[ch] + pos[ch];
  for (int i = d; i < TT * 16; i += 128) {
    (&S.sin_[0][0])[i] = (&g_sin[0][0])[i];
    (&S.cos_[0][0])[i] = (&g_cos[0][0])[i];
  }
  // zero the n=17 column of sT once (never rewritten)
  if (d < HH * TT) S.sT[d / TT][d % TT][17] = 0.f;
  __syncthreads();

  const float sgn = (ch & 1) ? 1.f : -1.f;
  const int dim = ch & 15;
  const int hh = d >> 5;
  const int tb = half ? 8 : 0;
  const int tc = half ? 9 : 8;
  const u64 one2 = pk2(1.f, 1.f);

  for (int L = 0; L < NLAYER; ++L) {
    // --- ln1 stats (warp-parallel) ---
    ln_stats(S, d);
    __syncthreads();
    {
      float sc = ln1_s[L * DD + ch], bi = ln1_b[L * DD + ch];
      for (int i = 0; i < tc; ++i) {
        int t = tb + i;
        S.xlT[ch][t] = (S.h[t][ch] - S.mu[t]) * S.rs[t] * sc + bi;
      }
      if (half) S.xlT[ch][17] = 0.f;  // token pad
    }
    __syncthreads();

    // --- fused QKVG projection (18-token pairs); v,g stay in registers ---
    float vv[18], gg[18];
    {
      u64 a0p[9], avp[9], agp[9];
#pragma unroll
      for (int i = 0; i < 9; ++i) { a0p[i] = 0; avp[i] = 0; agp[i] = 0; }
      const float* W0 = half ? (Wk + L * DD * QKD) : (Wq + L * DD * QKD);
      const float* Wv_ = Wv + L * DD * VDIM;
      const float* Wg_ = Wg + L * DD * VDIM;
      for (int e = 0; e < DD; ++e) {
        float w0 = W0[e * QKD + ch];
        float wv = Wv_[e * VDIM + d];
        float wg = Wg_[e * VDIM + d];
        u64 w0p = pk2(w0, w0), wvp = pk2(wv, wv), wgp = pk2(wg, wg);
        const float* xr = &S.xlT[e][0];
        u64 xv[9];
        ld128(xr, xv[0], xv[1]);
        ld128(xr + 4, xv[2], xv[3]);
        ld128(xr + 8, xv[4], xv[5]);
        ld128(xr + 12, xv[6], xv[7]);
        xv[8] = ld64(xr + 16);
#pragma unroll
        for (int i = 0; i < 9; ++i) {
          fma2(a0p[i], xv[i], w0p);
          fma2(avp[i], xv[i], wvp);
          fma2(agp[i], xv[i], wgp);
        }
      }
      float qa[18];
#pragma unroll
      for (int i = 0; i < 9; ++i) {
        up2(a0p[i], qa[2 * i], qa[2 * i + 1]);
        up2(avp[i], vv[2 * i], vv[2 * i + 1]);
        up2(agp[i], gg[2 * i], gg[2 * i + 1]);
      }
      // rotary on qa (t<17); write qT|kT as 64-bit pairs
      float r[18];
#pragma unroll
      for (int t = 0; t < TT; ++t) {
        float an = __shfl_xor_sync(0xffffffffu, qa[t], 1);
        float cs = S.cos_[t][dim], sn = S.sin_[t][dim];
        r[t] = qa[t] * cs + sgn * an * sn;
        if (half) r[t] *= 0.25f;
      }
      r[17] = 0.f;
      float* dst = half ? &S.kT[ch][0] : &S.qT[ch][0];
#pragma unroll
      for (int i = 0; i < 9; ++i) st64(dst + 2 * i, pk2(r[2 * i], r[2 * i + 1]));
    }
    __syncthreads();

    // --- scores: items (hs, n, m-group of 4), conflict-free reads ---
    for (int idx = d; idx < HH * TT * 5; idx += 128) {
      int mg = idx % 5;
      int rest = idx / 5;
      int n = rest % TT;
      int hs = rest / TT;
      u64 acc0 = 0, acc1 = 0;
      const float* qcol = &S.qT[hs * 16][n];
      const float* krow = &S.kT[hs * 16][4 * mg];
#pragma unroll
      for (int e = 0; e < 16; ++e) {
        float qs = qcol[e * 20];
        u64 k0, k1;
        ld128(krow + e * 20, k0, k1);
        u64 qp = pk2(qs, qs);
        fma2(acc0, qp, k0);
        fma2(acc1, qp, k1);
      }
      float s0, s1, s2, s3;
      up2(acc0, s0, s1);
      up2(acc1, s2, s3);
      const float* dm = &g_dmask[hs][n][4 * mg];
      int m0 = 4 * mg;
      S.sT[hs][m0][n] = s0 * dm[0];
      if (m0 + 1 < TT) S.sT[hs][m0 + 1][n] = s1 * dm[1];
      if (m0 + 2 < TT) S.sT[hs][m0 + 2][n] = s2 * dm[2];
      if (m0 + 3 < TT) S.sT[hs][m0 + 3][n] = s3 * dm[3];
    }
    __syncthreads();

    // --- s@v + denom (triangular); gnorm via warp shuffles; silu -> res ---
    float res[TT];
    {
      u64 ocp[9], dsp[9];
#pragma unroll
      for (int i = 0; i < 9; ++i) { ocp[i] = 0; dsp[i] = 0; }
      const float* sbase = &S.sT[hh][0][0];
#pragma unroll
      for (int m = 0; m < TT; ++m) {
        float vm = vv[m];
        u64 vmp = pk2(vm, vm);
        const float* sr = sbase + m * 20;
#pragma unroll
        for (int g = 0; g < 4; ++g) {
          if (g >= (m >> 2)) {  // groups with all n<m are exact zeros
            u64 sa, sb;
            ld128(sr + 4 * g, sa, sb);
            fma2(ocp[2 * g], sa, vmp);
            fma2(dsp[2 * g], sa, one2);
            fma2(ocp[2 * g + 1], sb, vmp);
            fma2(dsp[2 * g + 1], sb, one2);
          }
        }
        u64 s8 = ld64(sr + 16);
        fma2(ocp[8], s8, vmp);
        fma2(dsp[8], s8, one2);
      }
      float oc[18], ds[18];
#pragma unroll
      for (int i = 0; i < 9; ++i) {
        up2(ocp[i], oc[2 * i], oc[2 * i + 1]);
        up2(dsp[i], ds[2 * i], ds[2 * i + 1]);
      }
#pragma unroll
      for (int n = 0; n < TT; ++n) {
        float o = oc[n] / fmaxf(fabsf(ds[n]), 1.f);
        float s1 = o, s2 = o * o;
#pragma unroll
        for (int off = 16; off; off >>= 1) {
          s1 += __shfl_xor_sync(0xffffffffu, s1, off);
          s2 += __shfl_xor_sync(0xffffffffu, s2, off);
        }
        float mu = s1 * (1.f / 32.f);
        float grs = rsqrtf(s2 * (1.f / 32.f) - mu * mu + 1e-5f);
        float sg = gg[n] / (1.f + expf(-gg[n]));
        res[n] = sg * (o - mu) * grs;  // activation column c=d, token n
      }
    }
    // (no barrier: res is register-resident; Wo consumes via warp shfl)

    // --- output projection: warp-shfl outer product + smem atomics ---
    {
      const float* Wo_ = Wo + L * VDIM * DD;
      const int c0 = (d >> 5) << 5;  // warp's c-range base
      float accA[TT], accB[TT];
#pragma unroll
      for (int t = 0; t < TT; ++t) { accA[t] = 0.f; accB[t] = 0.f; }
      for (int s = 0; s < 32; ++s) {
        int c = c0 + s;
        float2 wv2 = *reinterpret_cast<const float2*>(Wo_ + c * DD + 2 * lane);
#pragma unroll
        for (int t = 0; t < TT; ++t) {
          float rt = __shfl_sync(0xffffffffu, res[t], s);
          accA[t] += wv2.x * rt;
          accB[t] += wv2.y * rt;
        }
      }
#pragma unroll
      for (int t = 0; t < TT; ++t) {
        atomicAdd(&S.h[t][2 * lane], accA[t]);
        atomicAdd(&S.h[t][2 * lane + 1], accB[t]);
      }
    }
    __syncthreads();

    // --- ln2 stats (warp-parallel) ---
    ln_stats(S, d);
    __syncthreads();
    {
      float sc = ln2_s[L * DD + ch], bi = ln2_b[L * DD + ch];
      for (int i = 0; i < tc; ++i) {
        int t = tb + i;
        S.xlT[ch][t] = (S.h[t][ch] - S.mu[t]) * S.rs[t] * sc + bi;
      }
      if (half) S.xlT[ch][17] = 0.f;
    }
    __syncthreads();
    // --- FFN fc1 + gelu(tanh) ---
    for (int idx = d; idx < TT * FFND; idx += 128) {
      int n = idx / FFND, j = idx - n * FFND;
      float acc = b1[L * FFND + j];
      for (int e = 0; e < DD; ++e)
        acc += S.xlT[e][n] * w1[(L * DD + e) * FFND + j];
      float c3 = acc * acc * acc;
      S.f[n][j] = 0.5f * acc *
                  (1.f + tanhf(0.7978845608028654f * (acc + 0.044715f * c3)));
    }
    __syncthreads();
    // --- FFN fc2 + residual ---
    {
      const float* W2 = w2 + L * FFND * DD + ch;
      float bb = b2[L * DD + ch];
      u64 wj[6];
#pragma unroll
      for (int jp = 0; jp < 6; ++jp)
        wj[jp] = pk2(W2[(2 * jp) * DD], W2[(2 * jp + 1) * DD]);
      for (int i = 0; i < tc; ++i) {
        int n = tb + i;
        const float* fr = &S.f[n][0];
        u64 f0, f1, f2, f3, f4, f5;
        ld128(fr, f0, f1);
        ld128(fr + 4, f2, f3);
        ld128(fr + 8, f4, f5);
        u64 acc = 0;
        fma2(acc, f0, wj[0]);
        fma2(acc, f1, wj[1]);
        fma2(acc, f2, wj[2]);
        fma2(acc, f3, wj[3]);
        fma2(acc, f4, wj[4]);
        fma2(acc, f5, wj[5]);
        float lo, hi;
        up2(acc, lo, hi);
        S.h[n][ch] += bb + lo + hi;
      }
    }
    __syncthreads();
  }

  // ---------------- final LN (token 16) + neck + head ----------------
  if (d == 0) {
    float s1 = 0.f, s2 = 0.f;
    for (int e = 0; e < DD; e += 4) {
      float4 v = *reinterpret_cast<const float4*>(&S.h[16][e]);
      s1 += (v.x + v.y) + (v.z + v.w);
      s2 += (v.x * v.x + v.y * v.y) + (v.z * v.z + v.w * v.w);
    }
    float mu = s1 * (1.f / DD);
    S.mu[0] = mu;
    S.rs[0] = rsqrtf(s2 * (1.f / DD) - mu * mu + 1e-5f);
  }
  __syncthreads();
  if (d < 64)
    S.xlT[d][0] = (S.h[16][d] - S.mu[0]) * S.rs[0] * lnf_s[d] + lnf_b[d];
  __syncthreads();
  if (d < 16) {
    float acc = neck_b[d];
    for (int e = 0; e < DD; ++e) acc += S.xlT[e][0] * neck_w[e * 16 + d];
    S.z[d] = acc;
  }
  __syncthreads();
  if (d < 10) {
    float acc = head_b[d];
#pragma unroll
    for (int uu = 0; uu < 16; ++uu) acc += S.z[uu] * head_w[uu * 10 + d];
    out[(size_t)b * 10 + d] = acc;
  }
}

extern "C" void kernel_launch(void* const* d_in, const int* in_sizes, int n_in,
                              void* d_out, int out_size) {
  const float* x = (const float*)d_in[0];
  const float* patch_w = (const float*)d_in[1];
  const float* patch_b = (const float*)d_in[2];
  const float* cls = (const float*)d_in[3];
  const float* pos = (const float*)d_in[4];
  const float* Wq = (const float*)d_in[5];
  const float* Wk = (const float*)d_in[6];
  const float* Wv = (const float*)d_in[7];
  const float* Wg = (const float*)d_in[8];
  const float* Wo = (const float*)d_in[9];
  const float* ln1_s = (const float*)d_in[10];
  const float* ln1_b = (const float*)d_in[11];
  const float* w1 = (const float*)d_in[12];
  const float* b1 = (const float*)d_in[13];
  const float* w2 = (const float*)d_in[14];
  const float* b2 = (const float*)d_in[15];
  const float* ln2_s = (const float*)d_in[16];
  const float* ln2_b = (const float*)d_in[17];
  const float* lnf_s = (const float*)d_in[18];
  const float* lnf_b = (const float*)d_in[19];
  const float* neck_w = (const float*)d_in[20];
  const float* neck_b = (const float*)d_in[21];
  const float* head_w = (const float*)d_in[22];
  const float* head_b = (const float*)d_in[23];
  float* out = (float*)d_out;

  int B = in_sizes[0] / 3072;
  size_t smem_bytes = sizeof(SmemU);
  (void)cudaFuncSetAttribute(
      vit_kernel, cudaFuncAttributeMaxDynamicSharedMemorySize, (int)smem_bytes);

  init_tables_kernel<<<1, 1>>>();
  vit_kernel<<<B, 128, smem_bytes>>>(x, patch_w, patch_b, cls, pos, Wq, Wk, Wv,
                                     Wg, Wo, ln1_s, ln1_b, w1, b1, w2, b2,
                                     ln2_s, ln2_b, lnf_s, lnf_b, neck_w, neck_b,
                                     head_w, head_b, out);
}

// round 14
// speedup vs baseline: 1.0242x; 1.0242x over previous
#include <cuda_runtime.h>
#include <math.h>

#define NLAYER 8
#define HH 4
#define DD 64
#define QKD 64
#define VDIM 128
#define TT 17
#define FFND 12

typedef unsigned long long u64;

// ---------------- f32x2 helpers ----------------
__device__ __forceinline__ u64 pk2(float a, float b) {
  u64 r;
  asm("mov.b64 %0, {%1,%2};" : "=l"(r) : "f"(a), "f"(b));
  return r;
}
__device__ __forceinline__ void up2(u64 v, float& a, float& b) {
  asm("mov.b64 {%0,%1}, %2;" : "=f"(a), "=f"(b) : "l"(v));
}
__device__ __forceinline__ void fma2(u64& d_, u64 a, u64 b) {
  asm("fma.rn.f32x2 %0, %1, %2, %0;" : "+l"(d_) : "l"(a), "l"(b));
}
__device__ __forceinline__ void ld128(const float* p, u64& a, u64& b) {
  float4 v = *reinterpret_cast<const float4*>(p);
  a = pk2(v.x, v.y);
  b = pk2(v.z, v.w);
}
__device__ __forceinline__ u64 ld64(const float* p) {
  return *reinterpret_cast<const u64*>(p);
}
__device__ __forceinline__ void st64(float* p, u64 v) {
  *reinterpret_cast<u64*>(p) = v;
}

// ---------------- precomputed tables ----------------
__device__ float g_sin[TT][16];
__device__ float g_cos[TT][16];
__device__ float g_dmask[HH][TT][20];  // padded rows (16B-aligned)

__global__ void init_tables_kernel() {
  if (threadIdx.x != 0 || blockIdx.x != 0) return;
  double angle[16];
  for (int u = 0; u < 8; ++u) {
    double a = pow(10000.0, -(double)u / 7.0);
    angle[2 * u] = a;
    angle[2 * u + 1] = a;
  }
  for (int t = 0; t < TT; ++t)
    for (int d2 = 0; d2 < 16; ++d2) {
      g_sin[t][d2] = (float)sin((double)t * angle[d2]);
      g_cos[t][d2] = (float)cos((double)t * angle[d2]);
    }
  double l0 = log(1.0 / 32.0), l1 = log(1.0 / 512.0);
  for (int h = 0; h < HH; ++h) {
    double gamma = 1.0 - exp(l0 + (double)h * (l1 - l0) / 3.0);
    for (int n = 0; n < TT; ++n) {
      double vals[TT];
      double rs = 0.0;
      for (int m = 0; m < TT; ++m) {
        double v_ = 0.0;
        if (n >= m) v_ = pow(gamma, (double)(n - m));
        vals[m] = v_;
        rs += v_;
      }
      double inv = 1.0 / sqrt(rs);
      for (int m = 0; m < TT; ++m) g_dmask[h][n][m] = (float)(vals[m] * inv);
      for (int m = TT; m < 20; ++m) g_dmask[h][n][m] = 0.f;
    }
  }
}

// ---------------- shared memory (vector bases 16B-aligned) ----------------
struct Smem {
  float h[TT][68];       // residual [t][ch]
  float xlT[DD][20];     // LN out [ch][t], t=17 pad 0
  float qT[DD][20];      // post-rotary q [ch][t]
  float kT[DD][20];      // post-rotary scaled k [ch][t]
  float gT[VDIM][20];    // [c][t]: raw g, then post-silu
  float sT[HH][TT][20];  // scores [h][m][n], n=17 col zeroed
  float f[TT][FFND];
  float sin_[TT][16], cos_[TT][16];
  float mu[TT], rs[TT];
  float z[16];
};
union SmemU {
  Smem a;
  float img[3 * 32 * 32];
};

// warp-parallel LN stats: warp w covers tokens 4w..4w+3 (+ token 16 on warp 0)
__device__ __forceinline__ void ln_stats(Smem& S, int d) {
  int wrp = d >> 5, lane = d & 31;
  int cnt = (wrp == 0) ? 5 : 4;
  for (int i = 0; i < cnt; ++i) {
    int t = (i == 4) ? 16 : (wrp * 4 + i);
    float a, b;
    up2(ld64(&S.h[t][2 * lane]), a, b);
    float s1 = a + b, s2 = a * a + b * b;
#pragma unroll
    for (int off = 16; off; off >>= 1) {
      s1 += __shfl_xor_sync(0xffffffffu, s1, off);
      s2 += __shfl_xor_sync(0xffffffffu, s2, off);
    }
    if (lane == 0) {
      float mu = s1 * (1.f / DD);
      S.mu[t] = mu;
      S.rs[t] = rsqrtf(s2 * (1.f / DD) - mu * mu + 1e-5f);
    }
  }
}

__global__ __launch_bounds__(128, 5) void vit_kernel(
    const float* __restrict__ x, const float* __restrict__ patch_w,
    const float* __restrict__ patch_b, const float* __restrict__ cls,
    const float* __restrict__ pos, const float* __restrict__ Wq,
    const float* __restrict__ Wk, const float* __restrict__ Wv,
    const float* __restrict__ Wg, const float* __restrict__ Wo,
    const float* __restrict__ ln1_s, const float* __restrict__ ln1_b,
    const float* __restrict__ w1, const float* __restrict__ b1,
    const float* __restrict__ w2, const float* __restrict__ b2,
    const float* __restrict__ ln2_s, const float* __restrict__ ln2_b,
    const float* __restrict__ lnf_s, const float* __restrict__ lnf_b,
    const float* __restrict__ neck_w, const float* __restrict__ neck_b,
    const float* __restrict__ head_w, const float* __restrict__ head_b,
    float* __restrict__ out) {
  extern __shared__ char smem_raw[];
  SmemU& U = *reinterpret_cast<SmemU*>(smem_raw);
  Smem& S = U.a;

  const int b = blockIdx.x;
  const int d = threadIdx.x;  // 0..127
  const int half = d >> 6;
  const int ch = d & 63;

  const float* xb = x + (size_t)b * 3072;
  for (int i = d; i < 3072; i += 128) U.img[i] = xb[i];
  __syncthreads();

  // ---------------- patch embedding ----------------
  float tokcol[8];
  const int pt0 = half ? 9 : 1;
  for (int i = 0; i < 8; ++i) {
    int t = pt0 + i;
    int p = t - 1, pr = p >> 2, pc = p & 3;
    float acc = patch_b[ch] + pos[t * DD + ch];
    u64 accp = 0;
    for (int c = 0; c < 3; ++c) {
#pragma unroll
      for (int i2 = 0; i2 < 8; ++i2) {
        const float* row = &U.img[c * 1024 + (pr * 8 + i2) * 32 + pc * 8];
        const float* wrow = &patch_w[(c * 64 + i2 * 8) * DD + ch];
        u64 r0, r1, r2, r3;
        ld128(row, r0, r1);
        ld128(row + 4, r2, r3);
        fma2(accp, r0, pk2(wrow[0], wrow[DD]));
        fma2(accp, r1, pk2(wrow[2 * DD], wrow[3 * DD]));
        fma2(accp, r2, pk2(wrow[4 * DD], wrow[5 * DD]));
        fma2(accp, r3, pk2(wrow[6 * DD], wrow[7 * DD]));
      }
    }
    float pa, pb;
    up2(accp, pa, pb);
    tokcol[i] = acc + pa + pb;
  }
  __syncthreads();  // img reads complete
#pragma unroll
  for (int i = 0; i < 8; ++i) S.h[pt0 + i][ch] = tokcol[i];
  if (half == 0) S.h[0][ch] = cls[ch] + pos[ch];
  for (int i = d; i < TT * 16; i += 128) {
    (&S.sin_[0][0])[i] = (&g_sin[0][0])[i];
    (&S.cos_[0][0])[i] = (&g_cos[0][0])[i];
  }
  // zero the n=17 column of sT once (never rewritten)
  if (d < HH * TT) S.sT[d / TT][d % TT][17] = 0.f;
  __syncthreads();

  const float sgn = (ch & 1) ? 1.f : -1.f;
  const int dim = ch & 15;
  const int hh = d >> 5;
  const int tb = half ? 8 : 0;
  const int tc = half ? 9 : 8;
  const u64 one2 = pk2(1.f, 1.f);

  for (int L = 0; L < NLAYER; ++L) {
    // --- ln1 stats (warp-parallel) ---
    ln_stats(S, d);
    __syncthreads();
    {
      float sc = ln1_s[L * DD + ch], bi = ln1_b[L * DD + ch];
      float rv[10];
      for (int i = 0; i < tc; ++i) {
        int t = tb + i;
        rv[i] = (S.h[t][ch] - S.mu[t]) * S.rs[t] * sc + bi;
      }
      if (half) {
        rv[9] = 0.f;  // token-17 pad
#pragma unroll
        for (int i = 0; i < 5; ++i)
          st64(&S.xlT[ch][8 + 2 * i], pk2(rv[2 * i], rv[2 * i + 1]));
      } else {
#pragma unroll
        for (int i = 0; i < 4; ++i)
          st64(&S.xlT[ch][2 * i], pk2(rv[2 * i], rv[2 * i + 1]));
      }
    }
    __syncthreads();

    // --- fused QKVG projection (18-token pairs); v in regs, g -> gT ---
    float vv[18];
    {
      u64 a0p[9], avp[9], agp[9];
#pragma unroll
      for (int i = 0; i < 9; ++i) { a0p[i] = 0; avp[i] = 0; agp[i] = 0; }
      const float* W0 = half ? (Wk + L * DD * QKD) : (Wq + L * DD * QKD);
      const float* Wv_ = Wv + L * DD * VDIM;
      const float* Wg_ = Wg + L * DD * VDIM;
      for (int e = 0; e < DD; ++e) {
        float w0 = W0[e * QKD + ch];
        float wv = Wv_[e * VDIM + d];
        float wg = Wg_[e * VDIM + d];
        u64 w0p = pk2(w0, w0), wvp = pk2(wv, wv), wgp = pk2(wg, wg);
        const float* xr = &S.xlT[e][0];
        u64 xv[9];
        ld128(xr, xv[0], xv[1]);
        ld128(xr + 4, xv[2], xv[3]);
        ld128(xr + 8, xv[4], xv[5]);
        ld128(xr + 12, xv[6], xv[7]);
        xv[8] = ld64(xr + 16);
#pragma unroll
        for (int i = 0; i < 9; ++i) {
          fma2(a0p[i], xv[i], w0p);
          fma2(avp[i], xv[i], wvp);
          fma2(agp[i], xv[i], wgp);
        }
      }
      float qa[18], gg[18];
#pragma unroll
      for (int i = 0; i < 9; ++i) {
        up2(a0p[i], qa[2 * i], qa[2 * i + 1]);
        up2(avp[i], vv[2 * i], vv[2 * i + 1]);
        up2(agp[i], gg[2 * i], gg[2 * i + 1]);
      }
      // rotary on qa (t<17); write qT|kT and raw gT as 64-bit pairs
      float r[18];
#pragma unroll
      for (int t = 0; t < TT; ++t) {
        float an = __shfl_xor_sync(0xffffffffu, qa[t], 1);
        float cs = S.cos_[t][dim], sn = S.sin_[t][dim];
        r[t] = qa[t] * cs + sgn * an * sn;
        if (half) r[t] *= 0.25f;
      }
      r[17] = 0.f;
      float* dst = half ? &S.kT[ch][0] : &S.qT[ch][0];
#pragma unroll
      for (int i = 0; i < 9; ++i) {
        st64(dst + 2 * i, pk2(r[2 * i], r[2 * i + 1]));
        st64(&S.gT[d][2 * i], pk2(gg[2 * i], gg[2 * i + 1]));
      }
    }
    __syncthreads();

    // --- scores: items (hs, n, m-group of 4); skip all-zero groups ---
    for (int idx = d; idx < HH * TT * 5; idx += 128) {
      int mg = idx % 5;
      int rest = idx / 5;
      int n = rest % TT;
      int hs = rest / TT;
      int m0 = 4 * mg;
      if (n < m0) {  // causal: all four outputs are exact zeros
        S.sT[hs][m0][n] = 0.f;
        if (m0 + 1 < TT) S.sT[hs][m0 + 1][n] = 0.f;
        if (m0 + 2 < TT) S.sT[hs][m0 + 2][n] = 0.f;
        if (m0 + 3 < TT) S.sT[hs][m0 + 3][n] = 0.f;
      } else {
        u64 acc0 = 0, acc1 = 0;
        const float* qcol = &S.qT[hs * 16][n];
        const float* krow = &S.kT[hs * 16][m0];
#pragma unroll
        for (int e = 0; e < 16; ++e) {
          float qs = qcol[e * 20];
          u64 k0, k1;
          ld128(krow + e * 20, k0, k1);
          u64 qp = pk2(qs, qs);
          fma2(acc0, qp, k0);
          fma2(acc1, qp, k1);
        }
        float s0, s1, s2, s3;
        up2(acc0, s0, s1);
        up2(acc1, s2, s3);
        const float* dm = &g_dmask[hs][n][m0];
        S.sT[hs][m0][n] = s0 * dm[0];
        if (m0 + 1 < TT) S.sT[hs][m0 + 1][n] = s1 * dm[1];
        if (m0 + 2 < TT) S.sT[hs][m0 + 2][n] = s2 * dm[2];
        if (m0 + 3 < TT) S.sT[hs][m0 + 3][n] = s3 * dm[3];
      }
    }
    __syncthreads();

    // --- s@v + denom (triangular); gnorm via warp shuffles; silu ---
    {
      u64 ocp[9], dsp[9];
#pragma unroll
      for (int i = 0; i < 9; ++i) { ocp[i] = 0; dsp[i] = 0; }
      const float* sbase = &S.sT[hh][0][0];
#pragma unroll
      for (int m = 0; m < TT; ++m) {
        float vm = vv[m];
        u64 vmp = pk2(vm, vm);
        const float* sr = sbase + m * 20;
#pragma unroll
        for (int g = 0; g < 4; ++g) {
          if (g >= (m >> 2)) {  // groups with all n<m are exact zeros
            u64 sa, sb;
            ld128(sr + 4 * g, sa, sb);
            fma2(ocp[2 * g], sa, vmp);
            fma2(dsp[2 * g], sa, one2);
            fma2(ocp[2 * g + 1], sb, vmp);
            fma2(dsp[2 * g + 1], sb, one2);
          }
        }
        u64 s8 = ld64(sr + 16);
        fma2(ocp[8], s8, vmp);
        fma2(dsp[8], s8, one2);
      }
      float oc[18], ds[18];
#pragma unroll
      for (int i = 0; i < 9; ++i) {
        up2(ocp[i], oc[2 * i], oc[2 * i + 1]);
        up2(dsp[i], ds[2 * i], ds[2 * i + 1]);
      }
      // load raw g pairs (own row)
      float gg[18];
#pragma unroll
      for (int i = 0; i < 9; ++i)
        up2(ld64(&S.gT[d][2 * i]), gg[2 * i], gg[2 * i + 1]);
      float res[18];
#pragma unroll
      for (int n = 0; n < TT; ++n) {
        float o = oc[n] / fmaxf(fabsf(ds[n]), 1.f);
        float s1 = o, s2 = o * o;
#pragma unroll
        for (int off = 16; off; off >>= 1) {
          s1 += __shfl_xor_sync(0xffffffffu, s1, off);
          s2 += __shfl_xor_sync(0xffffffffu, s2, off);
        }
        float mu = s1 * (1.f / 32.f);
        float grs = rsqrtf(s2 * (1.f / 32.f) - mu * mu + 1e-5f);
        float sg = gg[n] / (1.f + expf(-gg[n]));
        res[n] = sg * (o - mu) * grs;
      }
      res[17] = 0.f;
      __syncthreads();  // everyone done reading raw gT before overwrite
#pragma unroll
      for (int i = 0; i < 9; ++i)
        st64(&S.gT[d][2 * i], pk2(res[2 * i], res[2 * i + 1]));
    }
    __syncthreads();

    // --- output projection + residual ---
    {
      const float* Wo_ = Wo + L * VDIM * DD;
      u64 rcp[5];
#pragma unroll
      for (int i = 0; i < 5; ++i) rcp[i] = 0;
      for (int c = 0; c < VDIM; ++c) {
        float w = Wo_[c * DD + ch];
        u64 wp = pk2(w, w);
        const float* gr = &S.gT[c][tb];
        u64 g0, g1;
        ld128(gr, g0, g1);
        fma2(rcp[0], g0, wp);
        fma2(rcp[1], g1, wp);
        ld128(gr + 4, g0, g1);
        fma2(rcp[2], g0, wp);
        fma2(rcp[3], g1, wp);
        if (half) fma2(rcp[4], ld64(gr + 8), wp);  // tokens 16,17(=0)
      }
#pragma unroll
      for (int i = 0; i < 4; ++i) {
        float a, bq;
        up2(rcp[i], a, bq);
        S.h[tb + 2 * i][ch] += a;
        S.h[tb + 2 * i + 1][ch] += bq;
      }
      if (half) {
        float a, bq;
        up2(rcp[4], a, bq);
        S.h[16][ch] += a;
      }
    }
    __syncthreads();

    // --- ln2 stats (warp-parallel) ---
    ln_stats(S, d);
    __syncthreads();
    {
      float sc = ln2_s[L * DD + ch], bi = ln2_b[L * DD + ch];
      float rv[10];
      for (int i = 0; i < tc; ++i) {
        int t = tb + i;
        rv[i] = (S.h[t][ch] - S.mu[t]) * S.rs[t] * sc + bi;
      }
      if (half) {
        rv[9] = 0.f;
#pragma unroll
        for (int i = 0; i < 5; ++i)
          st64(&S.xlT[ch][8 + 2 * i], pk2(rv[2 * i], rv[2 * i + 1]));
      } else {
#pragma unroll
        for (int i = 0; i < 4; ++i)
          st64(&S.xlT[ch][2 * i], pk2(rv[2 * i], rv[2 * i + 1]));
      }
    }
    __syncthreads();
    // --- FFN fc1 + gelu(tanh), two hidden units per item ---
    if (d < TT * 6) {
      int n = d / 6, jp = d - n * 6;
      u64 acc = ld64(&b1[L * FFND + 2 * jp]);
      const float* W1 = w1 + (size_t)L * DD * FFND + 2 * jp;
      for (int e = 0; e < DD; ++e) {
        float xv = S.xlT[e][n];
        fma2(acc, pk2(xv, xv), ld64(W1 + e * FFND));
      }
      float a0, a1;
      up2(acc, a0, a1);
      float c30 = a0 * a0 * a0;
      float g0 =
          0.5f * a0 * (1.f + tanhf(0.7978845608028654f * (a0 + 0.044715f * c30)));
      float c31 = a1 * a1 * a1;
      float g1 =
          0.5f * a1 * (1.f + tanhf(0.7978845608028654f * (a1 + 0.044715f * c31)));
      st64(&S.f[n][2 * jp], pk2(g0, g1));
    }
    __syncthreads();
    // --- FFN fc2 + residual ---
    {
      const float* W2 = w2 + L * FFND * DD + ch;
      float bb = b2[L * DD + ch];
      u64 wj[6];
#pragma unroll
      for (int jp = 0; jp < 6; ++jp)
        wj[jp] = pk2(W2[(2 * jp) * DD], W2[(2 * jp + 1) * DD]);
      for (int i = 0; i < tc; ++i) {
        int n = tb + i;
        const float* fr = &S.f[n][0];
        u64 f0, f1, f2, f3, f4, f5;
        ld128(fr, f0, f1);
        ld128(fr + 4, f2, f3);
        ld128(fr + 8, f4, f5);
        u64 acc = 0;
        fma2(acc, f0, wj[0]);
        fma2(acc, f1, wj[1]);
        fma2(acc, f2, wj[2]);
        fma2(acc, f3, wj[3]);
        fma2(acc, f4, wj[4]);
        fma2(acc, f5, wj[5]);
        float lo, hi;
        up2(acc, lo, hi);
        S.h[n][ch] += bb + lo + hi;
      }
    }
    __syncthreads();
  }

  // ---------------- final LN (token 16) + neck + head ----------------
  if (d == 0) {
    float s1 = 0.f, s2 = 0.f;
    for (int e = 0; e < DD; e += 4) {
      float4 v = *reinterpret_cast<const float4*>(&S.h[16][e]);
      s1 += (v.x + v.y) + (v.z + v.w);
      s2 += (v.x * v.x + v.y * v.y) + (v.z * v.z + v.w * v.w);
    }
    float mu = s1 * (1.f / DD);
    S.mu[0] = mu;
    S.rs[0] = rsqrtf(s2 * (1.f / DD) - mu * mu + 1e-5f);
  }
  __syncthreads();
  if (d < 64)
    S.xlT[d][0] = (S.h[16][d] - S.mu[0]) * S.rs[0] * lnf_s[d] + lnf_b[d];
  __syncthreads();
  if (d < 16) {
    float acc = neck_b[d];
    for (int e = 0; e < DD; ++e) acc += S.xlT[e][0] * neck_w[e * 16 + d];
    S.z[d] = acc;
  }
  __syncthreads();
  if (d < 10) {
    float acc = head_b[d];
#pragma unroll
    for (int uu = 0; uu < 16; ++uu) acc += S.z[uu] * head_w[uu * 10 + d];
    out[(size_t)b * 10 + d] = acc;
  }
}

extern "C" void kernel_launch(void* const* d_in, const int* in_sizes, int n_in,
                              void* d_out, int out_size) {
  const float* x = (const float*)d_in[0];
  const float* patch_w = (const float*)d_in[1];
  const float* patch_b = (const float*)d_in[2];
  const float* cls = (const float*)d_in[3];
  const float* pos = (const float*)d_in[4];
  const float* Wq = (const float*)d_in[5];
  const float* Wk = (const float*)d_in[6];
  const float* Wv = (const float*)d_in[7];
  const float* Wg = (const float*)d_in[8];
  const float* Wo = (const float*)d_in[9];
  const float* ln1_s = (const float*)d_in[10];
  const float* ln1_b = (const float*)d_in[11];
  const float* w1 = (const float*)d_in[12];
  const float* b1 = (const float*)d_in[13];
  const float* w2 = (const float*)d_in[14];
  const float* b2 = (const float*)d_in[15];
  const float* ln2_s = (const float*)d_in[16];
  const float* ln2_b = (const float*)d_in[17];
  const float* lnf_s = (const float*)d_in[18];
  const float* lnf_b = (const float*)d_in[19];
  const float* neck_w = (const float*)d_in[20];
  const float* neck_b = (const float*)d_in[21];
  const float* head_w = (const float*)d_in[22];
  const float* head_b = (const float*)d_in[23];
  float* out = (float*)d_out;

  int B = in_sizes[0] / 3072;
  size_t smem_bytes = sizeof(SmemU);
  (void)cudaFuncSetAttribute(
      vit_kernel, cudaFuncAttributeMaxDynamicSharedMemorySize, (int)smem_bytes);

  init_tables_kernel<<<1, 1>>>();
  vit_kernel<<<B, 128, smem_bytes>>>(x, patch_w, patch_b, cls, pos, Wq, Wk, Wv,
                                     Wg, Wo, ln1_s, ln1_b, w1, b1, w2, b2,
                                     ln2_s, ln2_b, lnf_s, lnf_b, neck_w, neck_b,
                                     head_w, head_b, out);
}

// round 15
// speedup vs baseline: 1.0387x; 1.0142x over previous
#include <cuda_runtime.h>
#include <math.h>

#define NLAYER 8
#define HH 4
#define DD 64
#define QKD 64
#define VDIM 128
#define TT 17
#define FFND 12

typedef unsigned long long u64;

// ---------------- f32x2 helpers ----------------
__device__ __forceinline__ u64 pk2(float a, float b) {
  u64 r;
  asm("mov.b64 %0, {%1,%2};" : "=l"(r) : "f"(a), "f"(b));
  return r;
}
__device__ __forceinline__ void up2(u64 v, float& a, float& b) {
  asm("mov.b64 {%0,%1}, %2;" : "=f"(a), "=f"(b) : "l"(v));
}
__device__ __forceinline__ void fma2(u64& d_, u64 a, u64 b) {
  asm("fma.rn.f32x2 %0, %1, %2, %0;" : "+l"(d_) : "l"(a), "l"(b));
}
__device__ __forceinline__ void ld128(const float* p, u64& a, u64& b) {
  float4 v = *reinterpret_cast<const float4*>(p);
  a = pk2(v.x, v.y);
  b = pk2(v.z, v.w);
}
__device__ __forceinline__ u64 ld64(const float* p) {
  return *reinterpret_cast<const u64*>(p);
}
__device__ __forceinline__ void st64(float* p, u64 v) {
  *reinterpret_cast<u64*>(p) = v;
}

// ---------------- precomputed tables ----------------
__device__ float g_sin[TT][16];
__device__ float g_cos[TT][16];
__device__ float g_dmask[HH][TT][20];  // padded rows (16B-aligned)

__global__ void init_tables_kernel() {
  if (threadIdx.x != 0 || blockIdx.x != 0) return;
  double angle[16];
  for (int u = 0; u < 8; ++u) {
    double a = pow(10000.0, -(double)u / 7.0);
    angle[2 * u] = a;
    angle[2 * u + 1] = a;
  }
  for (int t = 0; t < TT; ++t)
    for (int d2 = 0; d2 < 16; ++d2) {
      g_sin[t][d2] = (float)sin((double)t * angle[d2]);
      g_cos[t][d2] = (float)cos((double)t * angle[d2]);
    }
  double l0 = log(1.0 / 32.0), l1 = log(1.0 / 512.0);
  for (int h = 0; h < HH; ++h) {
    double gamma = 1.0 - exp(l0 + (double)h * (l1 - l0) / 3.0);
    for (int n = 0; n < TT; ++n) {
      double vals[TT];
      double rs = 0.0;
      for (int m = 0; m < TT; ++m) {
        double v_ = 0.0;
        if (n >= m) v_ = pow(gamma, (double)(n - m));
        vals[m] = v_;
        rs += v_;
      }
      double inv = 1.0 / sqrt(rs);
      for (int m = 0; m < TT; ++m) g_dmask[h][n][m] = (float)(vals[m] * inv);
      for (int m = TT; m < 20; ++m) g_dmask[h][n][m] = 0.f;
    }
  }
}

// ---------------- shared memory (vector bases 16B-aligned) ----------------
#define NSC 45  // live (n, mg) score items per head (causal-compacted)
struct Smem {
  float h[TT][68];       // residual [t][ch]
  float xlT[DD][20];     // LN out [ch][t], t=17 pad 0
  float qT[DD][20];      // post-rotary q [ch][t]
  float kT[DD][20];      // post-rotary scaled k [ch][t]
  float gT[VDIM][20];    // [c][t]: raw g, then post-silu
  float sT[HH][TT][20];  // scores [h][m][n]; causal-zero region zeroed once
  float f[TT][FFND];
  float sin_[TT][16], cos_[TT][16];
  float mu[TT], rs[TT];
  float z[16];
  unsigned char sc_tab[48];  // compact item -> (n<<3)|mg
};
union SmemU {
  Smem a;
  float img[3 * 32 * 32];
};

// warp-parallel LN stats: warp w covers tokens 4w..4w+3 (+ token 16 on warp 0)
__device__ __forceinline__ void ln_stats(Smem& S, int d) {
  int wrp = d >> 5, lane = d & 31;
  int cnt = (wrp == 0) ? 5 : 4;
  for (int i = 0; i < cnt; ++i) {
    int t = (i == 4) ? 16 : (wrp * 4 + i);
    float a, b;
    up2(ld64(&S.h[t][2 * lane]), a, b);
    float s1 = a + b, s2 = a * a + b * b;
#pragma unroll
    for (int off = 16; off; off >>= 1) {
      s1 += __shfl_xor_sync(0xffffffffu, s1, off);
      s2 += __shfl_xor_sync(0xffffffffu, s2, off);
    }
    if (lane == 0) {
      float mu = s1 * (1.f / DD);
      S.mu[t] = mu;
      S.rs[t] = rsqrtf(s2 * (1.f / DD) - mu * mu + 1e-5f);
    }
  }
}

__global__ __launch_bounds__(128, 5) void vit_kernel(
    const float* __restrict__ x, const float* __restrict__ patch_w,
    const float* __restrict__ patch_b, const float* __restrict__ cls,
    const float* __restrict__ pos, const float* __restrict__ Wq,
    const float* __restrict__ Wk, const float* __restrict__ Wv,
    const float* __restrict__ Wg, const float* __restrict__ Wo,
    const float* __restrict__ ln1_s, const float* __restrict__ ln1_b,
    const float* __restrict__ w1, const float* __restrict__ b1,
    const float* __restrict__ w2, const float* __restrict__ b2,
    const float* __restrict__ ln2_s, const float* __restrict__ ln2_b,
    const float* __restrict__ lnf_s, const float* __restrict__ lnf_b,
    const float* __restrict__ neck_w, const float* __restrict__ neck_b,
    const float* __restrict__ head_w, const float* __restrict__ head_b,
    float* __restrict__ out) {
  extern __shared__ char smem_raw[];
  SmemU& U = *reinterpret_cast<SmemU*>(smem_raw);
  Smem& S = U.a;

  const int b = blockIdx.x;
  const int d = threadIdx.x;  // 0..127
  const int half = d >> 6;
  const int ch = d & 63;

  const float* xb = x + (size_t)b * 3072;
  for (int i = d; i < 3072; i += 128) U.img[i] = xb[i];
  __syncthreads();

  // ---------------- patch embedding ----------------
  float tokcol[8];
  const int pt0 = half ? 9 : 1;
  for (int i = 0; i < 8; ++i) {
    int t = pt0 + i;
    int p = t - 1, pr = p >> 2, pc = p & 3;
    float acc = patch_b[ch] + pos[t * DD + ch];
    u64 accp = 0;
    for (int c = 0; c < 3; ++c) {
#pragma unroll
      for (int i2 = 0; i2 < 8; ++i2) {
        const float* row = &U.img[c * 1024 + (pr * 8 + i2) * 32 + pc * 8];
        const float* wrow = &patch_w[(c * 64 + i2 * 8) * DD + ch];
        u64 r0, r1, r2, r3;
        ld128(row, r0, r1);
        ld128(row + 4, r2, r3);
        fma2(accp, r0, pk2(wrow[0], wrow[DD]));
        fma2(accp, r1, pk2(wrow[2 * DD], wrow[3 * DD]));
        fma2(accp, r2, pk2(wrow[4 * DD], wrow[5 * DD]));
        fma2(accp, r3, pk2(wrow[6 * DD], wrow[7 * DD]));
      }
    }
    float pa, pb;
    up2(accp, pa, pb);
    tokcol[i] = acc + pa + pb;
  }
  __syncthreads();  // img reads complete
#pragma unroll
  for (int i = 0; i < 8; ++i) S.h[pt0 + i][ch] = tokcol[i];
  if (half == 0) S.h[0][ch] = cls[ch] + pos[ch];
  for (int i = d; i < TT * 16; i += 128) {
    (&S.sin_[0][0])[i] = (&g_sin[0][0])[i];
    (&S.cos_[0][0])[i] = (&g_cos[0][0])[i];
  }
  // zero ALL of sT once: the causal-zero region is never touched again;
  // live entries are rewritten every layer before use.
  for (int i = d; i < HH * TT * 20; i += 128) (&S.sT[0][0][0])[i] = 0.f;
  // build compact score-item table: c -> (n<<3)|mg, mg <= n>>2
  if (d < NSC) {
    int bblk = (d < 4) ? 0 : (d < 12) ? 1 : (d < 24) ? 2 : (d < 40) ? 3 : 4;
    const int P[5] = {0, 4, 12, 24, 40};
    int r = d - P[bblk];
    int n = 4 * bblk + r / (bblk + 1);
    int mg = r - (r / (bblk + 1)) * (bblk + 1);
    S.sc_tab[d] = (unsigned char)((n << 3) | mg);
  }
  __syncthreads();

  const float sgn = (ch & 1) ? 1.f : -1.f;
  const int dim = ch & 15;
  const int hh = d >> 5;
  const int tb = half ? 8 : 0;
  const int tc = half ? 9 : 8;
  const u64 one2 = pk2(1.f, 1.f);

  for (int L = 0; L < NLAYER; ++L) {
    // --- ln1 stats (warp-parallel) ---
    ln_stats(S, d);
    __syncthreads();
    {
      float sc = ln1_s[L * DD + ch], bi = ln1_b[L * DD + ch];
      float rv[10];
      for (int i = 0; i < tc; ++i) {
        int t = tb + i;
        rv[i] = (S.h[t][ch] - S.mu[t]) * S.rs[t] * sc + bi;
      }
      if (half) {
        rv[9] = 0.f;  // token-17 pad
#pragma unroll
        for (int i = 0; i < 5; ++i)
          st64(&S.xlT[ch][8 + 2 * i], pk2(rv[2 * i], rv[2 * i + 1]));
      } else {
#pragma unroll
        for (int i = 0; i < 4; ++i)
          st64(&S.xlT[ch][2 * i], pk2(rv[2 * i], rv[2 * i + 1]));
      }
    }
    __syncthreads();

    // --- fused QKVG projection (18-token pairs); v in regs, g -> gT ---
    float vv[18];
    {
      u64 a0p[9], avp[9], agp[9];
#pragma unroll
      for (int i = 0; i < 9; ++i) { a0p[i] = 0; avp[i] = 0; agp[i] = 0; }
      const float* W0 = half ? (Wk + L * DD * QKD) : (Wq + L * DD * QKD);
      const float* Wv_ = Wv + L * DD * VDIM;
      const float* Wg_ = Wg + L * DD * VDIM;
      for (int e = 0; e < DD; ++e) {
        float w0 = W0[e * QKD + ch];
        float wv = Wv_[e * VDIM + d];
        float wg = Wg_[e * VDIM + d];
        u64 w0p = pk2(w0, w0), wvp = pk2(wv, wv), wgp = pk2(wg, wg);
        const float* xr = &S.xlT[e][0];
        u64 xv[9];
        ld128(xr, xv[0], xv[1]);
        ld128(xr + 4, xv[2], xv[3]);
        ld128(xr + 8, xv[4], xv[5]);
        ld128(xr + 12, xv[6], xv[7]);
        xv[8] = ld64(xr + 16);
#pragma unroll
        for (int i = 0; i < 9; ++i) {
          fma2(a0p[i], xv[i], w0p);
          fma2(avp[i], xv[i], wvp);
          fma2(agp[i], xv[i], wgp);
        }
      }
      float qa[18], gg[18];
#pragma unroll
      for (int i = 0; i < 9; ++i) {
        up2(a0p[i], qa[2 * i], qa[2 * i + 1]);
        up2(avp[i], vv[2 * i], vv[2 * i + 1]);
        up2(agp[i], gg[2 * i], gg[2 * i + 1]);
      }
      // rotary on qa (t<17); write qT|kT and raw gT as 64-bit pairs
      float r[18];
#pragma unroll
      for (int t = 0; t < TT; ++t) {
        float an = __shfl_xor_sync(0xffffffffu, qa[t], 1);
        float cs = S.cos_[t][dim], sn = S.sin_[t][dim];
        r[t] = qa[t] * cs + sgn * an * sn;
        if (half) r[t] *= 0.25f;
      }
      r[17] = 0.f;
      float* dst = half ? &S.kT[ch][0] : &S.qT[ch][0];
#pragma unroll
      for (int i = 0; i < 9; ++i) {
        st64(dst + 2 * i, pk2(r[2 * i], r[2 * i + 1]));
        st64(&S.gT[d][2 * i], pk2(gg[2 * i], gg[2 * i + 1]));
      }
    }
    __syncthreads();

    // --- scores: compacted live items only (mg <= n>>2), no divergence ---
    for (int idx = d; idx < HH * NSC; idx += 128) {
      int hs = idx / NSC;
      int c = idx - hs * NSC;
      int nm = S.sc_tab[c];
      int n = nm >> 3, mg = nm & 7;
      int m0 = 4 * mg;
      u64 acc0 = 0, acc1 = 0;
      const float* qcol = &S.qT[hs * 16][n];
      const float* krow = &S.kT[hs * 16][m0];
#pragma unroll
      for (int e = 0; e < 16; ++e) {
        float qs = qcol[e * 20];
        u64 k0, k1;
        ld128(krow + e * 20, k0, k1);
        u64 qp = pk2(qs, qs);
        fma2(acc0, qp, k0);
        fma2(acc1, qp, k1);
      }
      float s0, s1, s2, s3;
      up2(acc0, s0, s1);
      up2(acc1, s2, s3);
      const float* dm = &g_dmask[hs][n][m0];
      S.sT[hs][m0][n] = s0 * dm[0];
      if (m0 + 1 < TT) S.sT[hs][m0 + 1][n] = s1 * dm[1];
      if (m0 + 2 < TT) S.sT[hs][m0 + 2][n] = s2 * dm[2];
      if (m0 + 3 < TT) S.sT[hs][m0 + 3][n] = s3 * dm[3];
    }
    __syncthreads();

    // --- s@v + denom (triangular); gnorm via warp shuffles; silu ---
    {
      u64 ocp[9], dsp[9];
#pragma unroll
      for (int i = 0; i < 9; ++i) { ocp[i] = 0; dsp[i] = 0; }
      const float* sbase = &S.sT[hh][0][0];
#pragma unroll
      for (int m = 0; m < TT; ++m) {
        float vm = vv[m];
        u64 vmp = pk2(vm, vm);
        const float* sr = sbase + m * 20;
#pragma unroll
        for (int g = 0; g < 4; ++g) {
          if (g >= (m >> 2)) {  // groups with all n<m are exact zeros
            u64 sa, sb;
            ld128(sr + 4 * g, sa, sb);
            fma2(ocp[2 * g], sa, vmp);
            fma2(dsp[2 * g], sa, one2);
            fma2(ocp[2 * g + 1], sb, vmp);
            fma2(dsp[2 * g + 1], sb, one2);
          }
        }
        u64 s8 = ld64(sr + 16);
        fma2(ocp[8], s8, vmp);
        fma2(dsp[8], s8, one2);
      }
      float oc[18], ds[18];
#pragma unroll
      for (int i = 0; i < 9; ++i) {
        up2(ocp[i], oc[2 * i], oc[2 * i + 1]);
        up2(dsp[i], ds[2 * i], ds[2 * i + 1]);
      }
      // load raw g pairs (own row)
      float gg[18];
#pragma unroll
      for (int i = 0; i < 9; ++i)
        up2(ld64(&S.gT[d][2 * i]), gg[2 * i], gg[2 * i + 1]);
      float res[18];
#pragma unroll
      for (int n = 0; n < TT; ++n) {
        float o = oc[n] / fmaxf(fabsf(ds[n]), 1.f);
        float s1 = o, s2 = o * o;
#pragma unroll
        for (int off = 16; off; off >>= 1) {
          s1 += __shfl_xor_sync(0xffffffffu, s1, off);
          s2 += __shfl_xor_sync(0xffffffffu, s2, off);
        }
        float mu = s1 * (1.f / 32.f);
        float grs = rsqrtf(s2 * (1.f / 32.f) - mu * mu + 1e-5f);
        float sg = gg[n] / (1.f + expf(-gg[n]));
        res[n] = sg * (o - mu) * grs;
      }
      res[17] = 0.f;
      __syncthreads();  // everyone done reading raw gT before overwrite
#pragma unroll
      for (int i = 0; i < 9; ++i)
        st64(&S.gT[d][2 * i], pk2(res[2 * i], res[2 * i + 1]));
    }
    __syncthreads();

    // --- output projection + residual ---
    {
      const float* Wo_ = Wo + L * VDIM * DD;
      u64 rcp[5];
#pragma unroll
      for (int i = 0; i < 5; ++i) rcp[i] = 0;
      for (int c = 0; c < VDIM; ++c) {
        float w = Wo_[c * DD + ch];
        u64 wp = pk2(w, w);
        const float* gr = &S.gT[c][tb];
        u64 g0, g1;
        ld128(gr, g0, g1);
        fma2(rcp[0], g0, wp);
        fma2(rcp[1], g1, wp);
        ld128(gr + 4, g0, g1);
        fma2(rcp[2], g0, wp);
        fma2(rcp[3], g1, wp);
        if (half) fma2(rcp[4], ld64(gr + 8), wp);  // tokens 16,17(=0)
      }
#pragma unroll
      for (int i = 0; i < 4; ++i) {
        float a, bq;
        up2(rcp[i], a, bq);
        S.h[tb + 2 * i][ch] += a;
        S.h[tb + 2 * i + 1][ch] += bq;
      }
      if (half) {
        float a, bq;
        up2(rcp[4], a, bq);
        S.h[16][ch] += a;
      }
    }
    __syncthreads();

    // --- ln2 stats (warp-parallel) ---
    ln_stats(S, d);
    __syncthreads();
    {
      float sc = ln2_s[L * DD + ch], bi = ln2_b[L * DD + ch];
      float rv[10];
      for (int i = 0; i < tc; ++i) {
        int t = tb + i;
        rv[i] = (S.h[t][ch] - S.mu[t]) * S.rs[t] * sc + bi;
      }
      if (half) {
        rv[9] = 0.f;
#pragma unroll
        for (int i = 0; i < 5; ++i)
          st64(&S.xlT[ch][8 + 2 * i], pk2(rv[2 * i], rv[2 * i + 1]));
      } else {
#pragma unroll
        for (int i = 0; i < 4; ++i)
          st64(&S.xlT[ch][2 * i], pk2(rv[2 * i], rv[2 * i + 1]));
      }
    }
    __syncthreads();
    // --- FFN fc1 + gelu(tanh), two hidden units per item ---
    if (d < TT * 6) {
      int n = d / 6, jp = d - n * 6;
      u64 acc = ld64(&b1[L * FFND + 2 * jp]);
      const float* W1 = w1 + (size_t)L * DD * FFND + 2 * jp;
      for (int e = 0; e < DD; ++e) {
        float xv = S.xlT[e][n];
        fma2(acc, pk2(xv, xv), ld64(W1 + e * FFND));
      }
      float a0, a1;
      up2(acc, a0, a1);
      float c30 = a0 * a0 * a0;
      float g0 =
          0.5f * a0 * (1.f + tanhf(0.7978845608028654f * (a0 + 0.044715f * c30)));
      float c31 = a1 * a1 * a1;
      float g1 =
          0.5f * a1 * (1.f + tanhf(0.7978845608028654f * (a1 + 0.044715f * c31)));
      st64(&S.f[n][2 * jp], pk2(g0, g1));
    }
    __syncthreads();
    // --- FFN fc2 + residual ---
    {
      const float* W2 = w2 + L * FFND * DD + ch;
      float bb = b2[L * DD + ch];
      u64 wj[6];
#pragma unroll
      for (int jp = 0; jp < 6; ++jp)
        wj[jp] = pk2(W2[(2 * jp) * DD], W2[(2 * jp + 1) * DD]);
      for (int i = 0; i < tc; ++i) {
        int n = tb + i;
        const float* fr = &S.f[n][0];
        u64 f0, f1, f2, f3, f4, f5;
        ld128(fr, f0, f1);
        ld128(fr + 4, f2, f3);
        ld128(fr + 8, f4, f5);
        u64 acc = 0;
        fma2(acc, f0, wj[0]);
        fma2(acc, f1, wj[1]);
        fma2(acc, f2, wj[2]);
        fma2(acc, f3, wj[3]);
        fma2(acc, f4, wj[4]);
        fma2(acc, f5, wj[5]);
        float lo, hi;
        up2(acc, lo, hi);
        S.h[n][ch] += bb + lo + hi;
      }
    }
    __syncthreads();
  }

  // ---------------- final LN (token 16) + neck + head ----------------
  if (d == 0) {
    float s1 = 0.f, s2 = 0.f;
    for (int e = 0; e < DD; e += 4) {
      float4 v = *reinterpret_cast<const float4*>(&S.h[16][e]);
      s1 += (v.x + v.y) + (v.z + v.w);
      s2 += (v.x * v.x + v.y * v.y) + (v.z * v.z + v.w * v.w);
    }
    float mu = s1 * (1.f / DD);
    S.mu[0] = mu;
    S.rs[0] = rsqrtf(s2 * (1.f / DD) - mu * mu + 1e-5f);
  }
  __syncthreads();
  if (d < 64)
    S.xlT[d][0] = (S.h[16][d] - S.mu[0]) * S.rs[0] * lnf_s[d] + lnf_b[d];
  __syncthreads();
  if (d < 16) {
    float acc = neck_b[d];
    for (int e = 0; e < DD; ++e) acc += S.xlT[e][0] * neck_w[e * 16 + d];
    S.z[d] = acc;
  }
  __syncthreads();
  if (d < 10) {
    float acc = head_b[d];
#pragma unroll
    for (int uu = 0; uu < 16; ++uu) acc += S.z[uu] * head_w[uu * 10 + d];
    out[(size_t)b * 10 + d] = acc;
  }
}

extern "C" void kernel_launch(void* const* d_in, const int* in_sizes, int n_in,
                              void* d_out, int out_size) {
  const float* x = (const float*)d_in[0];
  const float* patch_w = (const float*)d_in[1];
  const float* patch_b = (const float*)d_in[2];
  const float* cls = (const float*)d_in[3];
  const float* pos = (const float*)d_in[4];
  const float* Wq = (const float*)d_in[5];
  const float* Wk = (const float*)d_in[6];
  const float* Wv = (const float*)d_in[7];
  const float* Wg = (const float*)d_in[8];
  const float* Wo = (const float*)d_in[9];
  const float* ln1_s = (const float*)d_in[10];
  const float* ln1_b = (const float*)d_in[11];
  const float* w1 = (const float*)d_in[12];
  const float* b1 = (const float*)d_in[13];
  const float* w2 = (const float*)d_in[14];
  const float* b2 = (const float*)d_in[15];
  const float* ln2_s = (const float*)d_in[16];
  const float* ln2_b = (const float*)d_in[17];
  const float* lnf_s = (const float*)d_in[18];
  const float* lnf_b = (const float*)d_in[19];
  const float* neck_w = (const float*)d_in[20];
  const float* neck_b = (const float*)d_in[21];
  const float* head_w = (const float*)d_in[22];
  const float* head_b = (const float*)d_in[23];
  float* out = (float*)d_out;

  int B = in_sizes[0] / 3072;
  size_t smem_bytes = sizeof(SmemU);
  (void)cudaFuncSetAttribute(
      vit_kernel, cudaFuncAttributeMaxDynamicSharedMemorySize, (int)smem_bytes);

  init_tables_kernel<<<1, 1>>>();
  vit_kernel<<<B, 128, smem_bytes>>>(x, patch_w, patch_b, cls, pos, Wq, Wk, Wv,
                                     Wg, Wo, ln1_s, ln1_b, w1, b1, w2, b2,
                                     ln2_s, ln2_b, lnf_s, lnf_b, neck_w, neck_b,
                                     head_w, head_b, out);
}

// round 16
// speedup vs baseline: 1.8157x; 1.7481x over previous
#include <cuda_runtime.h>
#include <math.h>

#define NLAYER 8
#define HH 4
#define DD 64
#define QKD 64
#define VDIM 128
#define TT 17
#define FFND 12

typedef unsigned long long u64;

// ---------------- f32x2 helpers ----------------
__device__ __forceinline__ u64 pk2(float a, float b) {
  u64 r;
  asm("mov.b64 %0, {%1,%2};" : "=l"(r) : "f"(a), "f"(b));
  return r;
}
__device__ __forceinline__ void up2(u64 v, float& a, float& b) {
  asm("mov.b64 {%0,%1}, %2;" : "=f"(a), "=f"(b) : "l"(v));
}
__device__ __forceinline__ void fma2(u64& d_, u64 a, u64 b) {
  asm("fma.rn.f32x2 %0, %1, %2, %0;" : "+l"(d_) : "l"(a), "l"(b));
}
__device__ __forceinline__ void ld128(const float* p, u64& a, u64& b) {
  float4 v = *reinterpret_cast<const float4*>(p);
  a = pk2(v.x, v.y);
  b = pk2(v.z, v.w);
}
__device__ __forceinline__ u64 ld64(const float* p) {
  return *reinterpret_cast<const u64*>(p);
}
__device__ __forceinline__ void st64(float* p, u64 v) {
  *reinterpret_cast<u64*>(p) = v;
}

// ---------------- precomputed tables ----------------
__device__ float g_sin[TT][16];
__device__ float g_cos[TT][16];
__device__ float g_dmask[HH][TT][20];  // padded rows (16B-aligned)

// PARALLEL table init: one thread per table entry / row.
// (The old single-thread version serialized ~1400 double-precision
// pow/sin/cos chains and cost 2.23 ms PER GRAPH REPLAY — 43% of runtime.)
__global__ void init_tables_kernel() {
  int t = threadIdx.x;
  if (t < TT * 16) {
    // rotary tables: one (token, dim) entry per thread
    int tok = t / 16, d2 = t - tok * 16;
    int u = d2 >> 1;
    double a = pow(10000.0, -(double)u / 7.0);
    g_sin[tok][d2] = (float)sin((double)tok * a);
    g_cos[tok][d2] = (float)cos((double)tok * a);
  }
  int r = t - TT * 16;
  if (r >= 0 && r < HH * TT) {
    // decay-mask: one (head, n) row per thread
    int h = r / TT, n = r - h * TT;
    double l0 = log(1.0 / 32.0), l1 = log(1.0 / 512.0);
    double gamma = 1.0 - exp(l0 + (double)h * (l1 - l0) / 3.0);
    double vals[TT];
    double rs = 0.0, p = 1.0;
    for (int m = n; m >= 0; --m) {  // gamma^(n-m) via iterative multiply
      vals[m] = p;
      rs += p;
      p *= gamma;
    }
    for (int m = n + 1; m < TT; ++m) vals[m] = 0.0;
    double inv = 1.0 / sqrt(rs);
    for (int m = 0; m < TT; ++m) g_dmask[h][n][m] = (float)(vals[m] * inv);
    for (int m = TT; m < 20; ++m) g_dmask[h][n][m] = 0.f;
  }
}

// ---------------- shared memory (vector bases 16B-aligned) ----------------
#define NSC 45  // live (n, mg) score items per head (causal-compacted)
struct Smem {
  float h[TT][68];       // residual [t][ch]
  float xlT[DD][20];     // LN out [ch][t], t=17 pad 0
  float qT[DD][20];      // post-rotary q [ch][t]
  float kT[DD][20];      // post-rotary scaled k [ch][t]
  float gT[VDIM][20];    // [c][t]: raw g, then post-silu
  float sT[HH][TT][20];  // scores [h][m][n]; causal-zero region zeroed once
  float f[TT][FFND];
  float sin_[TT][16], cos_[TT][16];
  float mu[TT], rs[TT];
  float z[16];
  unsigned char sc_tab[48];  // compact item -> (n<<3)|mg
};
union SmemU {
  Smem a;
  float img[3 * 32 * 32];
};

// warp-parallel LN stats: warp w covers tokens 4w..4w+3 (+ token 16 on warp 0)
__device__ __forceinline__ void ln_stats(Smem& S, int d) {
  int wrp = d >> 5, lane = d & 31;
  int cnt = (wrp == 0) ? 5 : 4;
  for (int i = 0; i < cnt; ++i) {
    int t = (i == 4) ? 16 : (wrp * 4 + i);
    float a, b;
    up2(ld64(&S.h[t][2 * lane]), a, b);
    float s1 = a + b, s2 = a * a + b * b;
#pragma unroll
    for (int off = 16; off; off >>= 1) {
      s1 += __shfl_xor_sync(0xffffffffu, s1, off);
      s2 += __shfl_xor_sync(0xffffffffu, s2, off);
    }
    if (lane == 0) {
      float mu = s1 * (1.f / DD);
      S.mu[t] = mu;
      S.rs[t] = rsqrtf(s2 * (1.f / DD) - mu * mu + 1e-5f);
    }
  }
}

__global__ __launch_bounds__(128, 5) void vit_kernel(
    const float* __restrict__ x, const float* __restrict__ patch_w,
    const float* __restrict__ patch_b, const float* __restrict__ cls,
    const float* __restrict__ pos, const float* __restrict__ Wq,
    const float* __restrict__ Wk, const float* __restrict__ Wv,
    const float* __restrict__ Wg, const float* __restrict__ Wo,
    const float* __restrict__ ln1_s, const float* __restrict__ ln1_b,
    const float* __restrict__ w1, const float* __restrict__ b1,
    const float* __restrict__ w2, const float* __restrict__ b2,
    const float* __restrict__ ln2_s, const float* __restrict__ ln2_b,
    const float* __restrict__ lnf_s, const float* __restrict__ lnf_b,
    const float* __restrict__ neck_w, const float* __restrict__ neck_b,
    const float* __restrict__ head_w, const float* __restrict__ head_b,
    float* __restrict__ out) {
  extern __shared__ char smem_raw[];
  SmemU& U = *reinterpret_cast<SmemU*>(smem_raw);
  Smem& S = U.a;

  const int b = blockIdx.x;
  const int d = threadIdx.x;  // 0..127
  const int half = d >> 6;
  const int ch = d & 63;

  const float* xb = x + (size_t)b * 3072;
  for (int i = d; i < 3072; i += 128) U.img[i] = xb[i];
  __syncthreads();

  // ---------------- patch embedding ----------------
  float tokcol[8];
  const int pt0 = half ? 9 : 1;
  for (int i = 0; i < 8; ++i) {
    int t = pt0 + i;
    int p = t - 1, pr = p >> 2, pc = p & 3;
    float acc = patch_b[ch] + pos[t * DD + ch];
    u64 accp = 0;
    for (int c = 0; c < 3; ++c) {
#pragma unroll
      for (int i2 = 0; i2 < 8; ++i2) {
        const float* row = &U.img[c * 1024 + (pr * 8 + i2) * 32 + pc * 8];
        const float* wrow = &patch_w[(c * 64 + i2 * 8) * DD + ch];
        u64 r0, r1, r2, r3;
        ld128(row, r0, r1);
        ld128(row + 4, r2, r3);
        fma2(accp, r0, pk2(wrow[0], wrow[DD]));
        fma2(accp, r1, pk2(wrow[2 * DD], wrow[3 * DD]));
        fma2(accp, r2, pk2(wrow[4 * DD], wrow[5 * DD]));
        fma2(accp, r3, pk2(wrow[6 * DD], wrow[7 * DD]));
      }
    }
    float pa, pb;
    up2(accp, pa, pb);
    tokcol[i] = acc + pa + pb;
  }
  __syncthreads();  // img reads complete
#pragma unroll
  for (int i = 0; i < 8; ++i) S.h[pt0 + i][ch] = tokcol[i];
  if (half == 0) S.h[0][ch] = cls[ch] + pos[ch];
  for (int i = d; i < TT * 16; i += 128) {
    (&S.sin_[0][0])[i] = (&g_sin[0][0])[i];
    (&S.cos_[0][0])[i] = (&g_cos[0][0])[i];
  }
  // zero ALL of sT once: the causal-zero region is never touched again;
  // live entries are rewritten every layer before use.
  for (int i = d; i < HH * TT * 20; i += 128) (&S.sT[0][0][0])[i] = 0.f;
  // build compact score-item table: c -> (n<<3)|mg, mg <= n>>2
  if (d < NSC) {
    int bblk = (d < 4) ? 0 : (d < 12) ? 1 : (d < 24) ? 2 : (d < 40) ? 3 : 4;
    const int P[5] = {0, 4, 12, 24, 40};
    int r = d - P[bblk];
    int n = 4 * bblk + r / (bblk + 1);
    int mg = r - (r / (bblk + 1)) * (bblk + 1);
    S.sc_tab[d] = (unsigned char)((n << 3) | mg);
  }
  __syncthreads();

  const float sgn = (ch & 1) ? 1.f : -1.f;
  const int dim = ch & 15;
  const int hh = d >> 5;
  const int tb = half ? 8 : 0;
  const int tc = half ? 9 : 8;
  const u64 one2 = pk2(1.f, 1.f);

  for (int L = 0; L < NLAYER; ++L) {
    // --- ln1 stats (warp-parallel) ---
    ln_stats(S, d);
    __syncthreads();
    {
      float sc = ln1_s[L * DD + ch], bi = ln1_b[L * DD + ch];
      float rv[10];
      for (int i = 0; i < tc; ++i) {
        int t = tb + i;
        rv[i] = (S.h[t][ch] - S.mu[t]) * S.rs[t] * sc + bi;
      }
      if (half) {
        rv[9] = 0.f;  // token-17 pad
#pragma unroll
        for (int i = 0; i < 5; ++i)
          st64(&S.xlT[ch][8 + 2 * i], pk2(rv[2 * i], rv[2 * i + 1]));
      } else {
#pragma unroll
        for (int i = 0; i < 4; ++i)
          st64(&S.xlT[ch][2 * i], pk2(rv[2 * i], rv[2 * i + 1]));
      }
    }
    __syncthreads();

    // --- fused QKVG projection (18-token pairs); v in regs, g -> gT ---
    float vv[18];
    {
      u64 a0p[9], avp[9], agp[9];
#pragma unroll
      for (int i = 0; i < 9; ++i) { a0p[i] = 0; avp[i] = 0; agp[i] = 0; }
      const float* W0 = half ? (Wk + L * DD * QKD) : (Wq + L * DD * QKD);
      const float* Wv_ = Wv + L * DD * VDIM;
      const float* Wg_ = Wg + L * DD * VDIM;
      for (int e = 0; e < DD; ++e) {
        float w0 = W0[e * QKD + ch];
        float wv = Wv_[e * VDIM + d];
        float wg = Wg_[e * VDIM + d];
        u64 w0p = pk2(w0, w0), wvp = pk2(wv, wv), wgp = pk2(wg, wg);
        const float* xr = &S.xlT[e][0];
        u64 xv[9];
        ld128(xr, xv[0], xv[1]);
        ld128(xr + 4, xv[2], xv[3]);
        ld128(xr + 8, xv[4], xv[5]);
        ld128(xr + 12, xv[6], xv[7]);
        xv[8] = ld64(xr + 16);
#pragma unroll
        for (int i = 0; i < 9; ++i) {
          fma2(a0p[i], xv[i], w0p);
          fma2(avp[i], xv[i], wvp);
          fma2(agp[i], xv[i], wgp);
        }
      }
      float qa[18], gg[18];
#pragma unroll
      for (int i = 0; i < 9; ++i) {
        up2(a0p[i], qa[2 * i], qa[2 * i + 1]);
        up2(avp[i], vv[2 * i], vv[2 * i + 1]);
        up2(agp[i], gg[2 * i], gg[2 * i + 1]);
      }
      // rotary on qa (t<17); write qT|kT and raw gT as 64-bit pairs
      float r[18];
#pragma unroll
      for (int t = 0; t < TT; ++t) {
        float an = __shfl_xor_sync(0xffffffffu, qa[t], 1);
        float cs = S.cos_[t][dim], sn = S.sin_[t][dim];
        r[t] = qa[t] * cs + sgn * an * sn;
        if (half) r[t] *= 0.25f;
      }
      r[17] = 0.f;
      float* dst = half ? &S.kT[ch][0] : &S.qT[ch][0];
#pragma unroll
      for (int i = 0; i < 9; ++i) {
        st64(dst + 2 * i, pk2(r[2 * i], r[2 * i + 1]));
        st64(&S.gT[d][2 * i], pk2(gg[2 * i], gg[2 * i + 1]));
      }
    }
    __syncthreads();

    // --- scores: compacted live items only (mg <= n>>2), no divergence ---
    for (int idx = d; idx < HH * NSC; idx += 128) {
      int hs = idx / NSC;
      int c = idx - hs * NSC;
      int nm = S.sc_tab[c];
      int n = nm >> 3, mg = nm & 7;
      int m0 = 4 * mg;
      u64 acc0 = 0, acc1 = 0;
      const float* qcol = &S.qT[hs * 16][n];
      const float* krow = &S.kT[hs * 16][m0];
#pragma unroll
      for (int e = 0; e < 16; ++e) {
        float qs = qcol[e * 20];
        u64 k0, k1;
        ld128(krow + e * 20, k0, k1);
        u64 qp = pk2(qs, qs);
        fma2(acc0, qp, k0);
        fma2(acc1, qp, k1);
      }
      float s0, s1, s2, s3;
      up2(acc0, s0, s1);
      up2(acc1, s2, s3);
      const float* dm = &g_dmask[hs][n][m0];
      S.sT[hs][m0][n] = s0 * dm[0];
      if (m0 + 1 < TT) S.sT[hs][m0 + 1][n] = s1 * dm[1];
      if (m0 + 2 < TT) S.sT[hs][m0 + 2][n] = s2 * dm[2];
      if (m0 + 3 < TT) S.sT[hs][m0 + 3][n] = s3 * dm[3];
    }
    __syncthreads();

    // --- s@v + denom (triangular); gnorm via warp shuffles; silu ---
    {
      u64 ocp[9], dsp[9];
#pragma unroll
      for (int i = 0; i < 9; ++i) { ocp[i] = 0; dsp[i] = 0; }
      const float* sbase = &S.sT[hh][0][0];
#pragma unroll
      for (int m = 0; m < TT; ++m) {
        float vm = vv[m];
        u64 vmp = pk2(vm, vm);
        const float* sr = sbase + m * 20;
#pragma unroll
        for (int g = 0; g < 4; ++g) {
          if (g >= (m >> 2)) {  // groups with all n<m are exact zeros
            u64 sa, sb;
            ld128(sr + 4 * g, sa, sb);
            fma2(ocp[2 * g], sa, vmp);
            fma2(dsp[2 * g], sa, one2);
            fma2(ocp[2 * g + 1], sb, vmp);
            fma2(dsp[2 * g + 1], sb, one2);
          }
        }
        u64 s8 = ld64(sr + 16);
        fma2(ocp[8], s8, vmp);
        fma2(dsp[8], s8, one2);
      }
      float oc[18], ds[18];
#pragma unroll
      for (int i = 0; i < 9; ++i) {
        up2(ocp[i], oc[2 * i], oc[2 * i + 1]);
        up2(dsp[i], ds[2 * i], ds[2 * i + 1]);
      }
      // load raw g pairs (own row)
      float gg[18];
#pragma unroll
      for (int i = 0; i < 9; ++i)
        up2(ld64(&S.gT[d][2 * i]), gg[2 * i], gg[2 * i + 1]);
      float res[18];
#pragma unroll
      for (int n = 0; n < TT; ++n) {
        float o = oc[n] / fmaxf(fabsf(ds[n]), 1.f);
        float s1 = o, s2 = o * o;
#pragma unroll
        for (int off = 16; off; off >>= 1) {
          s1 += __shfl_xor_sync(0xffffffffu, s1, off);
          s2 += __shfl_xor_sync(0xffffffffu, s2, off);
        }
        float mu = s1 * (1.f / 32.f);
        float grs = rsqrtf(s2 * (1.f / 32.f) - mu * mu + 1e-5f);
        float sg = gg[n] / (1.f + expf(-gg[n]));
        res[n] = sg * (o - mu) * grs;
      }
      res[17] = 0.f;
      __syncthreads();  // everyone done reading raw gT before overwrite
#pragma unroll
      for (int i = 0; i < 9; ++i)
        st64(&S.gT[d][2 * i], pk2(res[2 * i], res[2 * i + 1]));
    }
    __syncthreads();

    // --- output projection + residual ---
    {
      const float* Wo_ = Wo + L * VDIM * DD;
      u64 rcp[5];
#pragma unroll
      for (int i = 0; i < 5; ++i) rcp[i] = 0;
      for (int c = 0; c < VDIM; ++c) {
        float w = Wo_[c * DD + ch];
        u64 wp = pk2(w, w);
        const float* gr = &S.gT[c][tb];
        u64 g0, g1;
        ld128(gr, g0, g1);
        fma2(rcp[0], g0, wp);
        fma2(rcp[1], g1, wp);
        ld128(gr + 4, g0, g1);
        fma2(rcp[2], g0, wp);
        fma2(rcp[3], g1, wp);
        if (half) fma2(rcp[4], ld64(gr + 8), wp);  // tokens 16,17(=0)
      }
#pragma unroll
      for (int i = 0; i < 4; ++i) {
        float a, bq;
        up2(rcp[i], a, bq);
        S.h[tb + 2 * i][ch] += a;
        S.h[tb + 2 * i + 1][ch] += bq;
      }
      if (half) {
        float a, bq;
        up2(rcp[4], a, bq);
        S.h[16][ch] += a;
      }
    }
    __syncthreads();

    // --- ln2 stats (warp-parallel) ---
    ln_stats(S, d);
    __syncthreads();
    {
      float sc = ln2_s[L * DD + ch], bi = ln2_b[L * DD + ch];
      float rv[10];
      for (int i = 0; i < tc; ++i) {
        int t = tb + i;
        rv[i] = (S.h[t][ch] - S.mu[t]) * S.rs[t] * sc + bi;
      }
      if (half) {
        rv[9] = 0.f;
#pragma unroll
        for (int i = 0; i < 5; ++i)
          st64(&S.xlT[ch][8 + 2 * i], pk2(rv[2 * i], rv[2 * i + 1]));
      } else {
#pragma unroll
        for (int i = 0; i < 4; ++i)
          st64(&S.xlT[ch][2 * i], pk2(rv[2 * i], rv[2 * i + 1]));
      }
    }
    __syncthreads();
    // --- FFN fc1 + gelu(tanh), two hidden units per item ---
    if (d < TT * 6) {
      int n = d / 6, jp = d - n * 6;
      u64 acc = ld64(&b1[L * FFND + 2 * jp]);
      const float* W1 = w1 + (size_t)L * DD * FFND + 2 * jp;
      for (int e = 0; e < DD; ++e) {
        float xv = S.xlT[e][n];
        fma2(acc, pk2(xv, xv), ld64(W1 + e * FFND));
      }
      float a0, a1;
      up2(acc, a0, a1);
      float c30 = a0 * a0 * a0;
      float g0 =
          0.5f * a0 * (1.f + tanhf(0.7978845608028654f * (a0 + 0.044715f * c30)));
      float c31 = a1 * a1 * a1;
      float g1 =
          0.5f * a1 * (1.f + tanhf(0.7978845608028654f * (a1 + 0.044715f * c31)));
      st64(&S.f[n][2 * jp], pk2(g0, g1));
    }
    __syncthreads();
    // --- FFN fc2 + residual ---
    {
      const float* W2 = w2 + L * FFND * DD + ch;
      float bb = b2[L * DD + ch];
      u64 wj[6];
#pragma unroll
      for (int jp = 0; jp < 6; ++jp)
        wj[jp] = pk2(W2[(2 * jp) * DD], W2[(2 * jp + 1) * DD]);
      for (int i = 0; i < tc; ++i) {
        int n = tb + i;
        const float* fr = &S.f[n][0];
        u64 f0, f1, f2, f3, f4, f5;
        ld128(fr, f0, f1);
        ld128(fr + 4, f2, f3);
        ld128(fr + 8, f4, f5);
        u64 acc = 0;
        fma2(acc, f0, wj[0]);
        fma2(acc, f1, wj[1]);
        fma2(acc, f2, wj[2]);
        fma2(acc, f3, wj[3]);
        fma2(acc, f4, wj[4]);
        fma2(acc, f5, wj[5]);
        float lo, hi;
        up2(acc, lo, hi);
        S.h[n][ch] += bb + lo + hi;
      }
    }
    __syncthreads();
  }

  // ---------------- final LN (token 16) + neck + head ----------------
  if (d == 0) {
    float s1 = 0.f, s2 = 0.f;
    for (int e = 0; e < DD; e += 4) {
      float4 v = *reinterpret_cast<const float4*>(&S.h[16][e]);
      s1 += (v.x + v.y) + (v.z + v.w);
      s2 += (v.x * v.x + v.y * v.y) + (v.z * v.z + v.w * v.w);
    }
    float mu = s1 * (1.f / DD);
    S.mu[0] = mu;
    S.rs[0] = rsqrtf(s2 * (1.f / DD) - mu * mu + 1e-5f);
  }
  __syncthreads();
  if (d < 64)
    S.xlT[d][0] = (S.h[16][d] - S.mu[0]) * S.rs[0] * lnf_s[d] + lnf_b[d];
  __syncthreads();
  if (d < 16) {
    float acc = neck_b[d];
    for (int e = 0; e < DD; ++e) acc += S.xlT[e][0] * neck_w[e * 16 + d];
    S.z[d] = acc;
  }
  __syncthreads();
  if (d < 10) {
    float acc = head_b[d];
#pragma unroll
    for (int uu = 0; uu < 16; ++uu) acc += S.z[uu] * head_w[uu * 10 + d];
    out[(size_t)b * 10 + d] = acc;
  }
}

extern "C" void kernel_launch(void* const* d_in, const int* in_sizes, int n_in,
                              void* d_out, int out_size) {
  const float* x = (const float*)d_in[0];
  const float* patch_w = (const float*)d_in[1];
  const float* patch_b = (const float*)d_in[2];
  const float* cls = (const float*)d_in[3];
  const float* pos = (const float*)d_in[4];
  const float* Wq = (const float*)d_in[5];
  const float* Wk = (const float*)d_in[6];
  const float* Wv = (const float*)d_in[7];
  const float* Wg = (const float*)d_in[8];
  const float* Wo = (const float*)d_in[9];
  const float* ln1_s = (const float*)d_in[10];
  const float* ln1_b = (const float*)d_in[11];
  const float* w1 = (const float*)d_in[12];
  const float* b1 = (const float*)d_in[13];
  const float* w2 = (const float*)d_in[14];
  const float* b2 = (const float*)d_in[15];
  const float* ln2_s = (const float*)d_in[16];
  const float* ln2_b = (const float*)d_in[17];
  const float* lnf_s = (const float*)d_in[18];
  const float* lnf_b = (const float*)d_in[19];
  const float* neck_w = (const float*)d_in[20];
  const float* neck_b = (const float*)d_in[21];
  const float* head_w = (const float*)d_in[22];
  const float* head_b = (const float*)d_in[23];
  float* out = (float*)d_out;

  int B = in_sizes[0] / 3072;
  size_t smem_bytes = sizeof(SmemU);
  (void)cudaFuncSetAttribute(
      vit_kernel, cudaFuncAttributeMaxDynamicSharedMemorySize, (int)smem_bytes);

  init_tables_kernel<<<1, 352>>>();  // parallel: one entry/row per thread
  vit_kernel<<<B, 128, smem_bytes>>>(x, patch_w, patch_b, cls, pos, Wq, Wk, Wv,
                                     Wg, Wo, ln1_s, ln1_b, w1, b1, w2, b2,
                                     ln2_s, ln2_b, lnf_s, lnf_b, neck_w, neck_b,
                                     head_w, head_b, out);
}

// round 17
// speedup vs baseline: 1.9738x; 1.0871x over previous
#include <cuda_runtime.h>
#include <math.h>

#define NLAYER 8
#define HH 4
#define DD 64
#define QKD 64
#define VDIM 128
#define TT 17
#define FFND 12

typedef unsigned long long u64;

// ---------------- f32x2 helpers ----------------
__device__ __forceinline__ u64 pk2(float a, float b) {
  u64 r;
  asm("mov.b64 %0, {%1,%2};" : "=l"(r) : "f"(a), "f"(b));
  return r;
}
__device__ __forceinline__ void up2(u64 v, float& a, float& b) {
  asm("mov.b64 {%0,%1}, %2;" : "=f"(a), "=f"(b) : "l"(v));
}
__device__ __forceinline__ void fma2(u64& d_, u64 a, u64 b) {
  asm("fma.rn.f32x2 %0, %1, %2, %0;" : "+l"(d_) : "l"(a), "l"(b));
}
__device__ __forceinline__ void ld128(const float* p, u64& a, u64& b) {
  float4 v = *reinterpret_cast<const float4*>(p);
  a = pk2(v.x, v.y);
  b = pk2(v.z, v.w);
}
__device__ __forceinline__ u64 ld64(const float* p) {
  return *reinterpret_cast<const u64*>(p);
}
__device__ __forceinline__ void st64(float* p, u64 v) {
  *reinterpret_cast<u64*>(p) = v;
}

// ---------------- precomputed tables ----------------
__device__ float g_sin[TT][16];
__device__ float g_cos[TT][16];
__device__ float g_dmask[HH][TT][20];  // padded rows (16B-aligned)

// PARALLEL table init: one thread per table entry / row.
__global__ void init_tables_kernel() {
  int t = threadIdx.x;
  if (t < TT * 16) {
    int tok = t / 16, d2 = t - tok * 16;
    int u = d2 >> 1;
    double a = pow(10000.0, -(double)u / 7.0);
    g_sin[tok][d2] = (float)sin((double)tok * a);
    g_cos[tok][d2] = (float)cos((double)tok * a);
  }
  int r = t - TT * 16;
  if (r >= 0 && r < HH * TT) {
    int h = r / TT, n = r - h * TT;
    double l0 = log(1.0 / 32.0), l1 = log(1.0 / 512.0);
    double gamma = 1.0 - exp(l0 + (double)h * (l1 - l0) / 3.0);
    double vals[TT];
    double rs = 0.0, p = 1.0;
    for (int m = n; m >= 0; --m) {
      vals[m] = p;
      rs += p;
      p *= gamma;
    }
    for (int m = n + 1; m < TT; ++m) vals[m] = 0.0;
    double inv = 1.0 / sqrt(rs);
    for (int m = 0; m < TT; ++m) g_dmask[h][n][m] = (float)(vals[m] * inv);
    for (int m = TT; m < 20; ++m) g_dmask[h][n][m] = 0.f;
  }
}

// ---------------- shared memory (vector bases 16B-aligned) ----------------
#define NSC 45  // live (n, mg) score items per head (causal-compacted)
// xlT/qT/kT are all dead between the s@v stage and ln2 — the Wo partial
// buffer overlays them. (kT cols 18-19 garbage is only ever read into
// discarded lanes of the mg=4 score group, same as before.)
union Ov {
  struct {
    float xlT[DD][20];  // LN out [ch][t], t=17 pad 0
    float qT[DD][20];   // post-rotary q [ch][t]
    float kT[DD][20];   // post-rotary scaled k [ch][t]
  } a;                  // 3840 floats
  u64 pp[3][9][64];     // Wo partials: [warp][token-pair][channel] (3456 fl)
};
struct Smem {
  float h[TT][68];       // residual [t][ch]
  Ov ov;
  float gT[VDIM][20];    // [c][t]: raw g, then post-silu
  float sT[HH][TT][20];  // scores [h][m][n]; causal-zero region zeroed once
  float f[TT][FFND];
  float sin_[TT][16], cos_[TT][16];
  float mu[TT], rs[TT];
  float z[16];
  unsigned char sc_tab[48];  // compact item -> (n<<3)|mg
};
union SmemU {
  Smem a;
  float img[3 * 32 * 32];
};

// warp-parallel LN stats: warp w covers tokens 4w..4w+3 (+ token 16 on warp 0)
__device__ __forceinline__ void ln_stats(Smem& S, int d) {
  int wrp = d >> 5, lane = d & 31;
  int cnt = (wrp == 0) ? 5 : 4;
  for (int i = 0; i < cnt; ++i) {
    int t = (i == 4) ? 16 : (wrp * 4 + i);
    float a, b;
    up2(ld64(&S.h[t][2 * lane]), a, b);
    float s1 = a + b, s2 = a * a + b * b;
#pragma unroll
    for (int off = 16; off; off >>= 1) {
      s1 += __shfl_xor_sync(0xffffffffu, s1, off);
      s2 += __shfl_xor_sync(0xffffffffu, s2, off);
    }
    if (lane == 0) {
      float mu = s1 * (1.f / DD);
      S.mu[t] = mu;
      S.rs[t] = rsqrtf(s2 * (1.f / DD) - mu * mu + 1e-5f);
    }
  }
}

__global__ __launch_bounds__(128, 5) void vit_kernel(
    const float* __restrict__ x, const float* __restrict__ patch_w,
    const float* __restrict__ patch_b, const float* __restrict__ cls,
    const float* __restrict__ pos, const float* __restrict__ Wq,
    const float* __restrict__ Wk, const float* __restrict__ Wv,
    const float* __restrict__ Wg, const float* __restrict__ Wo,
    const float* __restrict__ ln1_s, const float* __restrict__ ln1_b,
    const float* __restrict__ w1, const float* __restrict__ b1,
    const float* __restrict__ w2, const float* __restrict__ b2,
    const float* __restrict__ ln2_s, const float* __restrict__ ln2_b,
    const float* __restrict__ lnf_s, const float* __restrict__ lnf_b,
    const float* __restrict__ neck_w, const float* __restrict__ neck_b,
    const float* __restrict__ head_w, const float* __restrict__ head_b,
    float* __restrict__ out) {
  extern __shared__ char smem_raw[];
  SmemU& U = *reinterpret_cast<SmemU*>(smem_raw);
  Smem& S = U.a;
  float(&xlT)[DD][20] = S.ov.a.xlT;
  float(&qT)[DD][20] = S.ov.a.qT;
  float(&kT)[DD][20] = S.ov.a.kT;

  const int b = blockIdx.x;
  const int d = threadIdx.x;  // 0..127
  const int half = d >> 6;
  const int ch = d & 63;

  const float* xb = x + (size_t)b * 3072;
  for (int i = d; i < 3072; i += 128) U.img[i] = xb[i];
  __syncthreads();

  // ---------------- patch embedding ----------------
  float tokcol[8];
  const int pt0 = half ? 9 : 1;
  for (int i = 0; i < 8; ++i) {
    int t = pt0 + i;
    int p = t - 1, pr = p >> 2, pc = p & 3;
    float acc = patch_b[ch] + pos[t * DD + ch];
    u64 accp = 0;
    for (int c = 0; c < 3; ++c) {
#pragma unroll
      for (int i2 = 0; i2 < 8; ++i2) {
        const float* row = &U.img[c * 1024 + (pr * 8 + i2) * 32 + pc * 8];
        const float* wrow = &patch_w[(c * 64 + i2 * 8) * DD + ch];
        u64 r0, r1, r2, r3;
        ld128(row, r0, r1);
        ld128(row + 4, r2, r3);
        fma2(accp, r0, pk2(wrow[0], wrow[DD]));
        fma2(accp, r1, pk2(wrow[2 * DD], wrow[3 * DD]));
        fma2(accp, r2, pk2(wrow[4 * DD], wrow[5 * DD]));
        fma2(accp, r3, pk2(wrow[6 * DD], wrow[7 * DD]));
      }
    }
    float pa, pb;
    up2(accp, pa, pb);
    tokcol[i] = acc + pa + pb;
  }
  __syncthreads();  // img reads complete
#pragma unroll
  for (int i = 0; i < 8; ++i) S.h[pt0 + i][ch] = tokcol[i];
  if (half == 0) S.h[0][ch] = cls[ch] + pos[ch];
  for (int i = d; i < TT * 16; i += 128) {
    (&S.sin_[0][0])[i] = (&g_sin[0][0])[i];
    (&S.cos_[0][0])[i] = (&g_cos[0][0])[i];
  }
  // zero ALL of sT once: the causal-zero region is never touched again
  for (int i = d; i < HH * TT * 20; i += 128) (&S.sT[0][0][0])[i] = 0.f;
  // build compact score-item table: c -> (n<<3)|mg, mg <= n>>2
  if (d < NSC) {
    int bblk = (d < 4) ? 0 : (d < 12) ? 1 : (d < 24) ? 2 : (d < 40) ? 3 : 4;
    const int P[5] = {0, 4, 12, 24, 40};
    int r = d - P[bblk];
    int n = 4 * bblk + r / (bblk + 1);
    int mg = r - (r / (bblk + 1)) * (bblk + 1);
    S.sc_tab[d] = (unsigned char)((n << 3) | mg);
  }
  __syncthreads();

  const float sgn = (ch & 1) ? 1.f : -1.f;
  const int dim = ch & 15;
  const int hh = d >> 5;
  const int tb = half ? 8 : 0;
  const int tc = half ? 9 : 8;
  const u64 one2 = pk2(1.f, 1.f);

  for (int L = 0; L < NLAYER; ++L) {
    // --- ln1 stats (warp-parallel) ---
    ln_stats(S, d);
    __syncthreads();
    {
      float sc = ln1_s[L * DD + ch], bi = ln1_b[L * DD + ch];
      float rv[10];
      for (int i = 0; i < tc; ++i) {
        int t = tb + i;
        rv[i] = (S.h[t][ch] - S.mu[t]) * S.rs[t] * sc + bi;
      }
      if (half) {
        rv[9] = 0.f;  // token-17 pad
#pragma unroll
        for (int i = 0; i < 5; ++i)
          st64(&xlT[ch][8 + 2 * i], pk2(rv[2 * i], rv[2 * i + 1]));
      } else {
#pragma unroll
        for (int i = 0; i < 4; ++i)
          st64(&xlT[ch][2 * i], pk2(rv[2 * i], rv[2 * i + 1]));
      }
    }
    __syncthreads();

    // --- fused QKVG projection (18-token pairs); v in regs, g -> gT ---
    float vv[18];
    {
      u64 a0p[9], avp[9], agp[9];
#pragma unroll
      for (int i = 0; i < 9; ++i) { a0p[i] = 0; avp[i] = 0; agp[i] = 0; }
      const float* W0 = half ? (Wk + L * DD * QKD) : (Wq + L * DD * QKD);
      const float* Wv_ = Wv + L * DD * VDIM;
      const float* Wg_ = Wg + L * DD * VDIM;
      for (int e = 0; e < DD; ++e) {
        float w0 = W0[e * QKD + ch];
        float wv = Wv_[e * VDIM + d];
        float wg = Wg_[e * VDIM + d];
        u64 w0p = pk2(w0, w0), wvp = pk2(wv, wv), wgp = pk2(wg, wg);
        const float* xr = &xlT[e][0];
        u64 xv[9];
        ld128(xr, xv[0], xv[1]);
        ld128(xr + 4, xv[2], xv[3]);
        ld128(xr + 8, xv[4], xv[5]);
        ld128(xr + 12, xv[6], xv[7]);
        xv[8] = ld64(xr + 16);
#pragma unroll
        for (int i = 0; i < 9; ++i) {
          fma2(a0p[i], xv[i], w0p);
          fma2(avp[i], xv[i], wvp);
          fma2(agp[i], xv[i], wgp);
        }
      }
      float qa[18], gg[18];
#pragma unroll
      for (int i = 0; i < 9; ++i) {
        up2(a0p[i], qa[2 * i], qa[2 * i + 1]);
        up2(avp[i], vv[2 * i], vv[2 * i + 1]);
        up2(agp[i], gg[2 * i], gg[2 * i + 1]);
      }
      // rotary on qa (t<17); write qT|kT and raw gT as 64-bit pairs
      float r[18];
#pragma unroll
      for (int t = 0; t < TT; ++t) {
        float an = __shfl_xor_sync(0xffffffffu, qa[t], 1);
        float cs = S.cos_[t][dim], sn = S.sin_[t][dim];
        r[t] = qa[t] * cs + sgn * an * sn;
        if (half) r[t] *= 0.25f;
      }
      r[17] = 0.f;
      float* dst = half ? &kT[ch][0] : &qT[ch][0];
#pragma unroll
      for (int i = 0; i < 9; ++i) {
        st64(dst + 2 * i, pk2(r[2 * i], r[2 * i + 1]));
        st64(&S.gT[d][2 * i], pk2(gg[2 * i], gg[2 * i + 1]));
      }
    }
    __syncthreads();

    // --- scores: compacted live items only (mg <= n>>2), no divergence ---
    for (int idx = d; idx < HH * NSC; idx += 128) {
      int hs = idx / NSC;
      int c = idx - hs * NSC;
      int nm = S.sc_tab[c];
      int n = nm >> 3, mg = nm & 7;
      int m0 = 4 * mg;
      u64 acc0 = 0, acc1 = 0;
      const float* qcol = &qT[hs * 16][n];
      const float* krow = &kT[hs * 16][m0];
#pragma unroll
      for (int e = 0; e < 16; ++e) {
        float qs = qcol[e * 20];
        u64 k0, k1;
        ld128(krow + e * 20, k0, k1);
        u64 qp = pk2(qs, qs);
        fma2(acc0, qp, k0);
        fma2(acc1, qp, k1);
      }
      float s0, s1, s2, s3;
      up2(acc0, s0, s1);
      up2(acc1, s2, s3);
      const float* dm = &g_dmask[hs][n][m0];
      S.sT[hs][m0][n] = s0 * dm[0];
      if (m0 + 1 < TT) S.sT[hs][m0 + 1][n] = s1 * dm[1];
      if (m0 + 2 < TT) S.sT[hs][m0 + 2][n] = s2 * dm[2];
      if (m0 + 3 < TT) S.sT[hs][m0 + 3][n] = s3 * dm[3];
    }
    __syncthreads();

    // --- s@v + denom (triangular); gnorm via warp shuffles; silu ---
    {
      u64 ocp[9], dsp[9];
#pragma unroll
      for (int i = 0; i < 9; ++i) { ocp[i] = 0; dsp[i] = 0; }
      const float* sbase = &S.sT[hh][0][0];
#pragma unroll
      for (int m = 0; m < TT; ++m) {
        float vm = vv[m];
        u64 vmp = pk2(vm, vm);
        const float* sr = sbase + m * 20;
#pragma unroll
        for (int g = 0; g < 4; ++g) {
          if (g >= (m >> 2)) {  // groups with all n<m are exact zeros
            u64 sa, sb;
            ld128(sr + 4 * g, sa, sb);
            fma2(ocp[2 * g], sa, vmp);
            fma2(dsp[2 * g], sa, one2);
            fma2(ocp[2 * g + 1], sb, vmp);
            fma2(dsp[2 * g + 1], sb, one2);
          }
        }
        u64 s8 = ld64(sr + 16);
        fma2(ocp[8], s8, vmp);
        fma2(dsp[8], s8, one2);
      }
      float oc[18], ds[18];
#pragma unroll
      for (int i = 0; i < 9; ++i) {
        up2(ocp[i], oc[2 * i], oc[2 * i + 1]);
        up2(dsp[i], ds[2 * i], ds[2 * i + 1]);
      }
      // load raw g pairs (own row)
      float gg[18];
#pragma unroll
      for (int i = 0; i < 9; ++i)
        up2(ld64(&S.gT[d][2 * i]), gg[2 * i], gg[2 * i + 1]);
      float res[18];
#pragma unroll
      for (int n = 0; n < TT; ++n) {
        float o = oc[n] / fmaxf(fabsf(ds[n]), 1.f);
        float s1 = o, s2 = o * o;
#pragma unroll
        for (int off = 16; off; off >>= 1) {
          s1 += __shfl_xor_sync(0xffffffffu, s1, off);
          s2 += __shfl_xor_sync(0xffffffffu, s2, off);
        }
        float mu = s1 * (1.f / 32.f);
        float grs = rsqrtf(s2 * (1.f / 32.f) - mu * mu + 1e-5f);
        float sg = gg[n] / (1.f + expf(-gg[n]));
        res[n] = sg * (o - mu) * grs;
      }
      res[17] = 0.f;
      __syncthreads();  // everyone done reading raw gT before overwrite
#pragma unroll
      for (int i = 0; i < 9; ++i)
        st64(&S.gT[d][2 * i], pk2(res[2 * i], res[2 * i + 1]));
    }
    __syncthreads();

    // --- output projection stage 1: warp w owns c in [32w,32w+32),
    //     lane l owns channels {2l,2l+1}; all 18 tokens packed ---
    {
      const int w = d >> 5, l = d & 31;
      const float* Wb = Wo + L * VDIM * DD + (32 * w) * DD + 2 * l;
      u64 accA[9], accB[9];
#pragma unroll
      for (int i = 0; i < 9; ++i) { accA[i] = 0; accB[i] = 0; }
      for (int cc = 0; cc < 32; ++cc) {
        float2 wv = *reinterpret_cast<const float2*>(Wb + cc * DD);
        u64 wxa = pk2(wv.x, wv.x), wxb = pk2(wv.y, wv.y);
        const float* gr = &S.gT[32 * w + cc][0];
        u64 xv[9];
        ld128(gr, xv[0], xv[1]);
        ld128(gr + 4, xv[2], xv[3]);
        ld128(gr + 8, xv[4], xv[5]);
        ld128(gr + 12, xv[6], xv[7]);
        xv[8] = ld64(gr + 16);
#pragma unroll
        for (int i = 0; i < 9; ++i) {
          fma2(accA[i], xv[i], wxa);
          fma2(accB[i], xv[i], wxb);
        }
      }
      if (w < 3) {
        // store packed partials: pp[w][pair][channel]
#pragma unroll
        for (int i = 0; i < 9; ++i) {
          S.ov.pp[w][i][2 * l] = accA[i];
          S.ov.pp[w][i][2 * l + 1] = accB[i];
        }
      } else {
        // warp 3 adds its partial directly into h (tokens < 17 only)
#pragma unroll
        for (int i = 0; i < 9; ++i) {
          float a0, a1, b0, b1;
          up2(accA[i], a0, a1);
          up2(accB[i], b0, b1);
          int t0 = 2 * i, t1 = 2 * i + 1;
          float h0, h1;
          up2(ld64(&S.h[t0][2 * l]), h0, h1);
          st64(&S.h[t0][2 * l], pk2(h0 + a0, h1 + b0));
          if (t1 < TT) {
            up2(ld64(&S.h[t1][2 * l]), h0, h1);
            st64(&S.h[t1][2 * l], pk2(h0 + a1, h1 + b1));
          }
        }
      }
    }
    __syncthreads();
    // --- stage 2: sum the 3 stored partials into h ---
    {
      int ip0 = half ? 4 : 0, ipc = half ? 5 : 4;
      for (int i = 0; i < ipc; ++i) {
        int ip = ip0 + i;
        u64 acc = 0;
        fma2(acc, S.ov.pp[0][ip][ch], one2);
        fma2(acc, S.ov.pp[1][ip][ch], one2);
        fma2(acc, S.ov.pp[2][ip][ch], one2);
        float a0, a1;
        up2(acc, a0, a1);
        int t0 = 2 * ip, t1 = t0 + 1;
        S.h[t0][ch] += a0;
        if (t1 < TT) S.h[t1][ch] += a1;
      }
    }
    __syncthreads();

    // --- ln2 stats (warp-parallel) ---
    ln_stats(S, d);
    __syncthreads();
    {
      float sc = ln2_s[L * DD + ch], bi = ln2_b[L * DD + ch];
      float rv[10];
      for (int i = 0; i < tc; ++i) {
        int t = tb + i;
        rv[i] = (S.h[t][ch] - S.mu[t]) * S.rs[t] * sc + bi;
      }
      if (half) {
        rv[9] = 0.f;
#pragma unroll
        for (int i = 0; i < 5; ++i)
          st64(&xlT[ch][8 + 2 * i], pk2(rv[2 * i], rv[2 * i + 1]));
      } else {
#pragma unroll
        for (int i = 0; i < 4; ++i)
          st64(&xlT[ch][2 * i], pk2(rv[2 * i], rv[2 * i + 1]));
      }
    }
    __syncthreads();
    // --- FFN fc1 + gelu(tanh), two hidden units per item ---
    if (d < TT * 6) {
      int n = d / 6, jp = d - n * 6;
      u64 acc = ld64(&b1[L * FFND + 2 * jp]);
      const float* W1 = w1 + (size_t)L * DD * FFND + 2 * jp;
      for (int e = 0; e < DD; ++e) {
        float xv = xlT[e][n];
        fma2(acc, pk2(xv, xv), ld64(W1 + e * FFND));
      }
      float a0, a1;
      up2(acc, a0, a1);
      float c30 = a0 * a0 * a0;
      float g0 =
          0.5f * a0 * (1.f + tanhf(0.7978845608028654f * (a0 + 0.044715f * c30)));
      float c31 = a1 * a1 * a1;
      float g1 =
          0.5f * a1 * (1.f + tanhf(0.7978845608028654f * (a1 + 0.044715f * c31)));
      st64(&S.f[n][2 * jp], pk2(g0, g1));
    }
    __syncthreads();
    // --- FFN fc2 + residual ---
    {
      const float* W2 = w2 + L * FFND * DD + ch;
      float bb = b2[L * DD + ch];
      u64 wj[6];
#pragma unroll
      for (int jp = 0; jp < 6; ++jp)
        wj[jp] = pk2(W2[(2 * jp) * DD], W2[(2 * jp + 1) * DD]);
      for (int i = 0; i < tc; ++i) {
        int n = tb + i;
        const float* fr = &S.f[n][0];
        u64 f0, f1, f2, f3, f4, f5;
        ld128(fr, f0, f1);
        ld128(fr + 4, f2, f3);
        ld128(fr + 8, f4, f5);
        u64 acc = 0;
        fma2(acc, f0, wj[0]);
        fma2(acc, f1, wj[1]);
        fma2(acc, f2, wj[2]);
        fma2(acc, f3, wj[3]);
        fma2(acc, f4, wj[4]);
        fma2(acc, f5, wj[5]);
        float lo, hi;
        up2(acc, lo, hi);
        S.h[n][ch] += bb + lo + hi;
      }
    }
    __syncthreads();
  }

  // ---------------- final LN (token 16) + neck + head ----------------
  if (d == 0) {
    float s1 = 0.f, s2 = 0.f;
    for (int e = 0; e < DD; e += 4) {
      float4 v = *reinterpret_cast<const float4*>(&S.h[16][e]);
      s1 += (v.x + v.y) + (v.z + v.w);
      s2 += (v.x * v.x + v.y * v.y) + (v.z * v.z + v.w * v.w);
    }
    float mu = s1 * (1.f / DD);
    S.mu[0] = mu;
    S.rs[0] = rsqrtf(s2 * (1.f / DD) - mu * mu + 1e-5f);
  }
  __syncthreads();
  if (d < 64)
    xlT[d][0] = (S.h[16][d] - S.mu[0]) * S.rs[0] * lnf_s[d] + lnf_b[d];
  __syncthreads();
  if (d < 16) {
    float acc = neck_b[d];
    for (int e = 0; e < DD; ++e) acc += xlT[e][0] * neck_w[e * 16 + d];
    S.z[d] = acc;
  }
  __syncthreads();
  if (d < 10) {
    float acc = head_b[d];
#pragma unroll
    for (int uu = 0; uu < 16; ++uu) acc += S.z[uu] * head_w[uu * 10 + d];
    out[(size_t)b * 10 + d] = acc;
  }
}

extern "C" void kernel_launch(void* const* d_in, const int* in_sizes, int n_in,
                              void* d_out, int out_size) {
  const float* x = (const float*)d_in[0];
  const float* patch_w = (const float*)d_in[1];
  const float* patch_b = (const float*)d_in[2];
  const float* cls = (const float*)d_in[3];
  const float* pos = (const float*)d_in[4];
  const float* Wq = (const float*)d_in[5];
  const float* Wk = (const float*)d_in[6];
  const float* Wv = (const float*)d_in[7];
  const float* Wg = (const float*)d_in[8];
  const float* Wo = (const float*)d_in[9];
  const float* ln1_s = (const float*)d_in[10];
  const float* ln1_b = (const float*)d_in[11];
  const float* w1 = (const float*)d_in[12];
  const float* b1 = (const float*)d_in[13];
  const float* w2 = (const float*)d_in[14];
  const float* b2 = (const float*)d_in[15];
  const float* ln2_s = (const float*)d_in[16];
  const float* ln2_b = (const float*)d_in[17];
  const float* lnf_s = (const float*)d_in[18];
  const float* lnf_b = (const float*)d_in[19];
  const float* neck_w = (const float*)d_in[20];
  const float* neck_b = (const float*)d_in[21];
  const float* head_w = (const float*)d_in[22];
  const float* head_b = (const float*)d_in[23];
  float* out = (float*)d_out;

  int B = in_sizes[0] / 3072;
  size_t smem_bytes = sizeof(SmemU);
  (void)cudaFuncSetAttribute(
      vit_kernel, cudaFuncAttributeMaxDynamicSharedMemorySize, (int)smem_bytes);

  init_tables_kernel<<<1, 352>>>();
  vit_kernel<<<B, 128, smem_bytes>>>(x, patch_w, patch_b, cls, pos, Wq, Wk, Wv,
                                     Wg, Wo, ln1_s, ln1_b, w1, b1, w2, b2,
                                     ln2_s, ln2_b, lnf_s, lnf_b, neck_w, neck_b,
                                     head_w, head_b, out);
}